// round 1
// baseline (speedup 1.0000x reference)
#include <cuda_runtime.h>
#include <math.h>

#define BATCH 4
#define SEQ   2048
#define DM    512
#define NH    8
#define DK    64
#define ROWS  (BATCH * SEQ)   // 8192

// ---------------- scratch (static device globals: allowed) ----------------
__device__ float g_pe[SEQ * DM];     // positional encoding table
__device__ float g_h [ROWS * DM];    // h = LN1(x) + pe   (residual1)
__device__ float g_q [ROWS * DM];    // q proj, later reused for o@wfc
__device__ float g_k [ROWS * DM];
__device__ float g_v [ROWS * DM];
__device__ float g_o [ROWS * DM];    // attention output

// ---------------- positional encoding (fp64 for accuracy) ----------------
__global__ void pe_kernel(float* __restrict__ pe) {
    int t   = blockIdx.x;          // 0..2047
    int tid = threadIdx.x;         // 256 threads
    const double c = -(9.210340371976184 / 512.0);   // -ln(10000)/512
#pragma unroll
    for (int u = 0; u < 2; u++) {
        int col = tid + u * 256;
        int i2  = col & ~1;
        double arg = (double)t * exp((double)i2 * c);
        pe[t * DM + col] = (col & 1) ? (float)cos(arg) : (float)sin(arg);
    }
}

// ---------------- LN1 + pe ----------------
__global__ void ln1_pos_kernel(const float* __restrict__ x,
                               const float* __restrict__ gam,
                               const float* __restrict__ bet,
                               const float* __restrict__ pe,
                               float* __restrict__ h) {
    __shared__ float redS[8], redS2[8];
    int row = blockIdx.x;
    int t   = row & (SEQ - 1);
    const float* xr = x  + (size_t)row * DM;
    float*       hr = h  + (size_t)row * DM;
    const float* pr = pe + (size_t)t   * DM;
    int tid = threadIdx.x;

    float a = xr[tid], b = xr[tid + 256];
    float s  = a + b;
    float s2 = a * a + b * b;
#pragma unroll
    for (int off = 16; off; off >>= 1) {
        s  += __shfl_xor_sync(0xffffffffu, s,  off);
        s2 += __shfl_xor_sync(0xffffffffu, s2, off);
    }
    if ((tid & 31) == 0) { redS[tid >> 5] = s; redS2[tid >> 5] = s2; }
    __syncthreads();
    if (tid == 0) {
        float S = 0.f, S2 = 0.f;
#pragma unroll
        for (int w = 0; w < 8; w++) { S += redS[w]; S2 += redS2[w]; }
        redS[0] = S; redS2[0] = S2;
    }
    __syncthreads();
    float mu   = redS[0] * (1.f / 512.f);
    float var  = redS2[0] * (1.f / 512.f) - mu * mu;
    float rstd = rsqrtf(var + 1e-5f);

#pragma unroll
    for (int u = 0; u < 2; u++) {
        int col = tid + u * 256;
        float xv = u ? b : a;
        hr[col] = (xv - mu) * rstd * gam[col] + bet[col] + pr[col];
    }
}

// ---------------- LN2 + residuals ----------------
__global__ void ln2_kernel(const float* __restrict__ o2,
                           const float* __restrict__ r1,
                           const float* __restrict__ x,
                           const float* __restrict__ gam,
                           const float* __restrict__ bet,
                           float* __restrict__ out) {
    __shared__ float redS[8], redS2[8];
    int row = blockIdx.x;
    const float* or_ = o2 + (size_t)row * DM;
    const float* rr  = r1 + (size_t)row * DM;
    const float* xr  = x  + (size_t)row * DM;
    float*       wr  = out + (size_t)row * DM;
    int tid = threadIdx.x;

    float a = or_[tid]       + rr[tid];
    float b = or_[tid + 256] + rr[tid + 256];
    float s  = a + b;
    float s2 = a * a + b * b;
#pragma unroll
    for (int off = 16; off; off >>= 1) {
        s  += __shfl_xor_sync(0xffffffffu, s,  off);
        s2 += __shfl_xor_sync(0xffffffffu, s2, off);
    }
    if ((tid & 31) == 0) { redS[tid >> 5] = s; redS2[tid >> 5] = s2; }
    __syncthreads();
    if (tid == 0) {
        float S = 0.f, S2 = 0.f;
#pragma unroll
        for (int w = 0; w < 8; w++) { S += redS[w]; S2 += redS2[w]; }
        redS[0] = S; redS2[0] = S2;
    }
    __syncthreads();
    float mu   = redS[0] * (1.f / 512.f);
    float var  = redS2[0] * (1.f / 512.f) - mu * mu;
    float rstd = rsqrtf(var + 1e-6f);

#pragma unroll
    for (int u = 0; u < 2; u++) {
        int col = tid + u * 256;
        float vv = u ? b : a;
        wr[col] = (vv - mu) * rstd * gam[col] + bet[col] + xr[col];
    }
}

// ---------------- GEMM: C[M,512] = A[M,512] @ W[512,512], fp32 ----------------
__global__ void __launch_bounds__(256)
gemm512_kernel(const float* __restrict__ A,
               const float* __restrict__ W,
               float* __restrict__ C) {
    __shared__ float As[16][65];   // transposed A tile, padded
    __shared__ float Bs[16][64];
    int m0 = blockIdx.x * 64;
    int n0 = blockIdx.y * 64;
    int tid = threadIdx.x;
    int tx = tid & 15, ty = tid >> 4;

    float acc[4][4];
#pragma unroll
    for (int i = 0; i < 4; i++)
#pragma unroll
        for (int j = 0; j < 4; j++) acc[i][j] = 0.f;

    for (int k0 = 0; k0 < 512; k0 += 16) {
        {   // load A 64x16 (transposed into As)
            int r = tid >> 2, c4 = tid & 3;
            float4 av = *(const float4*)(A + (size_t)(m0 + r) * DM + k0 + c4 * 4);
            As[c4 * 4 + 0][r] = av.x;
            As[c4 * 4 + 1][r] = av.y;
            As[c4 * 4 + 2][r] = av.z;
            As[c4 * 4 + 3][r] = av.w;
        }
        {   // load W 16x64
            int r = tid >> 4, c = tid & 15;
            *(float4*)(&Bs[r][c * 4]) =
                *(const float4*)(W + (size_t)(k0 + r) * DM + n0 + c * 4);
        }
        __syncthreads();
#pragma unroll
        for (int kk = 0; kk < 16; kk++) {
            float av[4], bv[4];
#pragma unroll
            for (int i = 0; i < 4; i++) av[i] = As[kk][ty + 16 * i];
#pragma unroll
            for (int j = 0; j < 4; j++) bv[j] = Bs[kk][tx + 16 * j];
#pragma unroll
            for (int i = 0; i < 4; i++)
#pragma unroll
                for (int j = 0; j < 4; j++) acc[i][j] += av[i] * bv[j];
        }
        __syncthreads();
    }
#pragma unroll
    for (int i = 0; i < 4; i++)
#pragma unroll
        for (int j = 0; j < 4; j++)
            C[(size_t)(m0 + ty + 16 * i) * DM + n0 + tx + 16 * j] = acc[i][j];
}

// ---------------- causal flash attention, fp32, 64x64 tiles ----------------
// q,k,v layout: [B, T, H*DK] (head hd occupies cols hd*64 .. hd*64+63)
#define SQ_STRIDE 68
#define SP_STRIDE 65

__global__ void __launch_bounds__(256)
attn_kernel(const float* __restrict__ Q,
            const float* __restrict__ K,
            const float* __restrict__ V,
            float* __restrict__ O) {
    extern __shared__ float sm[];
    float* sQ = sm;                              // 64 x 68
    float* sK = sQ + 64 * SQ_STRIDE;             // 64 x 68
    float* sV = sK + 64 * SQ_STRIDE;             // 64 x 64
    float* sP = sV + 64 * 64;                    // 64 x 65

    int qt = blockIdx.x;               // query tile 0..31
    int bh = blockIdx.y;               // 0..31
    int bb = bh >> 3, hd = bh & 7;
    int tid = threadIdx.x;
    int tx = tid & 15, ty = tid >> 4;

    size_t base = ((size_t)bb * SEQ) * DM + (size_t)hd * DK;

    // load Q tile (pre-scaled by 1/sqrt(64))
    for (int i = tid; i < 64 * 16; i += 256) {
        int r = i >> 4, c4 = i & 15;
        float4 qv = *(const float4*)(Q + base + (size_t)(qt * 64 + r) * DM + c4 * 4);
        qv.x *= 0.125f; qv.y *= 0.125f; qv.z *= 0.125f; qv.w *= 0.125f;
        *(float4*)(&sQ[r * SQ_STRIDE + c4 * 4]) = qv;
    }

    float Oacc[4][4];
    float m_i[4], l_i[4];
#pragma unroll
    for (int i = 0; i < 4; i++) {
        m_i[i] = -1e30f; l_i[i] = 0.f;
#pragma unroll
        for (int j = 0; j < 4; j++) Oacc[i][j] = 0.f;
    }

    for (int kt = 0; kt <= qt; kt++) {
        // load K,V tiles
        for (int i = tid; i < 64 * 16; i += 256) {
            int r = i >> 4, c4 = i & 15;
            size_t ga = base + (size_t)(kt * 64 + r) * DM + c4 * 4;
            *(float4*)(&sK[r * SQ_STRIDE + c4 * 4]) = *(const float4*)(K + ga);
            *(float4*)(&sV[r * 64        + c4 * 4]) = *(const float4*)(V + ga);
        }
        __syncthreads();

        // S = Q K^T  (thread owns rows ty+16i, cols tx+16j)
        float s[4][4];
#pragma unroll
        for (int i = 0; i < 4; i++)
#pragma unroll
            for (int j = 0; j < 4; j++) s[i][j] = 0.f;

#pragma unroll
        for (int d4 = 0; d4 < 16; d4++) {
            float4 qv[4], kv[4];
#pragma unroll
            for (int i = 0; i < 4; i++)
                qv[i] = *(const float4*)(&sQ[(ty + 16 * i) * SQ_STRIDE + d4 * 4]);
#pragma unroll
            for (int j = 0; j < 4; j++)
                kv[j] = *(const float4*)(&sK[(tx + 16 * j) * SQ_STRIDE + d4 * 4]);
#pragma unroll
            for (int i = 0; i < 4; i++)
#pragma unroll
                for (int j = 0; j < 4; j++)
                    s[i][j] += qv[i].x * kv[j].x + qv[i].y * kv[j].y +
                               qv[i].z * kv[j].z + qv[i].w * kv[j].w;
        }

        if (kt == qt) {   // causal mask on diagonal tile
#pragma unroll
            for (int i = 0; i < 4; i++)
#pragma unroll
                for (int j = 0; j < 4; j++)
                    if (tx + 16 * j > ty + 16 * i) s[i][j] = -1e30f;
        }

        // online softmax per query row (row spans 16 lanes: xor masks < 16)
#pragma unroll
        for (int i = 0; i < 4; i++) {
            float mt = fmaxf(fmaxf(s[i][0], s[i][1]), fmaxf(s[i][2], s[i][3]));
#pragma unroll
            for (int off = 8; off; off >>= 1)
                mt = fmaxf(mt, __shfl_xor_sync(0xffffffffu, mt, off));
            float mn   = fmaxf(m_i[i], mt);
            float corr = expf(m_i[i] - mn);
            m_i[i] = mn;
            float rs = 0.f;
#pragma unroll
            for (int j = 0; j < 4; j++) {
                float p = expf(s[i][j] - mn);
                s[i][j] = p;
                rs += p;
            }
#pragma unroll
            for (int off = 8; off; off >>= 1)
                rs += __shfl_xor_sync(0xffffffffu, rs, off);
            l_i[i] = l_i[i] * corr + rs;
#pragma unroll
            for (int j = 0; j < 4; j++) Oacc[i][j] *= corr;
#pragma unroll
            for (int j = 0; j < 4; j++)
                sP[(ty + 16 * i) * SP_STRIDE + tx + 16 * j] = s[i][j];
        }
        __syncthreads();

        // O += P V   (thread owns rows ty+16i, dims tx+16j)
#pragma unroll 4
        for (int k = 0; k < 64; k++) {
            float pv[4], vv[4];
#pragma unroll
            for (int i = 0; i < 4; i++) pv[i] = sP[(ty + 16 * i) * SP_STRIDE + k];
#pragma unroll
            for (int j = 0; j < 4; j++) vv[j] = sV[k * 64 + tx + 16 * j];
#pragma unroll
            for (int i = 0; i < 4; i++)
#pragma unroll
                for (int j = 0; j < 4; j++) Oacc[i][j] += pv[i] * vv[j];
        }
        __syncthreads();
    }

    // epilogue: normalize and store
#pragma unroll
    for (int i = 0; i < 4; i++) {
        float inv = 1.f / l_i[i];
        size_t rowa = base + (size_t)(qt * 64 + ty + 16 * i) * DM;
#pragma unroll
        for (int j = 0; j < 4; j++)
            O[rowa + tx + 16 * j] = Oacc[i][j] * inv;
    }
}

// ---------------- launch ----------------
extern "C" void kernel_launch(void* const* d_in, const int* in_sizes, int n_in,
                              void* d_out, int out_size) {
    const float* x     = (const float*)d_in[0];
    const float* ln1_g = (const float*)d_in[1];
    const float* ln1_b = (const float*)d_in[2];
    const float* wq    = (const float*)d_in[3];
    const float* wk    = (const float*)d_in[4];
    const float* wv    = (const float*)d_in[5];
    const float* wfc   = (const float*)d_in[6];
    const float* ln2_g = (const float*)d_in[7];
    const float* ln2_b = (const float*)d_in[8];
    float* out = (float*)d_out;

    float *ppe, *ph, *pq, *pk, *pv, *po;
    cudaGetSymbolAddress((void**)&ppe, g_pe);
    cudaGetSymbolAddress((void**)&ph,  g_h);
    cudaGetSymbolAddress((void**)&pq,  g_q);
    cudaGetSymbolAddress((void**)&pk,  g_k);
    cudaGetSymbolAddress((void**)&pv,  g_v);
    cudaGetSymbolAddress((void**)&po,  g_o);

    static const int kAttnSmem = (64 * SQ_STRIDE * 2 + 64 * 64 + 64 * SP_STRIDE) * 4;
    cudaFuncSetAttribute(attn_kernel,
                         cudaFuncAttributeMaxDynamicSharedMemorySize, kAttnSmem);

    pe_kernel<<<SEQ, 256>>>(ppe);
    ln1_pos_kernel<<<ROWS, 256>>>(x, ln1_g, ln1_b, ppe, ph);

    dim3 gg(ROWS / 64, DM / 64);
    gemm512_kernel<<<gg, 256>>>(ph, wq, pq);
    gemm512_kernel<<<gg, 256>>>(ph, wk, pk);
    gemm512_kernel<<<gg, 256>>>(ph, wv, pv);

    dim3 ga(SEQ / 64, BATCH * NH);
    attn_kernel<<<ga, 256, kAttnSmem>>>(pq, pk, pv, po);

    gemm512_kernel<<<gg, 256>>>(po, wfc, pq);   // reuse g_q as o@wfc scratch

    ln2_kernel<<<ROWS, 256>>>(pq, ph, x, ln2_g, ln2_b, out);
}

// round 2
// speedup vs baseline: 1.1969x; 1.1969x over previous
#include <cuda_runtime.h>
#include <math.h>

#define BATCH 4
#define SEQ   2048
#define DM    512
#define NH    8
#define DK    64
#define ROWS  (BATCH * SEQ)   // 8192

// ---------------- scratch ----------------
__device__ float g_pe[SEQ * DM];
__device__ float g_h [ROWS * DM];
__device__ float g_q [ROWS * DM];
__device__ float g_k [ROWS * DM];
__device__ float g_v [ROWS * DM];
__device__ float g_o [ROWS * DM];

// ---------------- positional encoding (fp64) ----------------
__global__ void pe_kernel(float* __restrict__ pe) {
    int t   = blockIdx.x;
    int tid = threadIdx.x;
    const double c = -(9.210340371976184 / 512.0);
#pragma unroll
    for (int u = 0; u < 2; u++) {
        int col = tid + u * 256;
        int i2  = col & ~1;
        double arg = (double)t * exp((double)i2 * c);
        pe[t * DM + col] = (col & 1) ? (float)cos(arg) : (float)sin(arg);
    }
}

// ---------------- LN1 + pe ----------------
__global__ void ln1_pos_kernel(const float* __restrict__ x,
                               const float* __restrict__ gam,
                               const float* __restrict__ bet,
                               const float* __restrict__ pe,
                               float* __restrict__ h) {
    __shared__ float redS[8], redS2[8];
    int row = blockIdx.x;
    int t   = row & (SEQ - 1);
    const float* xr = x  + (size_t)row * DM;
    float*       hr = h  + (size_t)row * DM;
    const float* pr = pe + (size_t)t   * DM;
    int tid = threadIdx.x;

    float a = xr[tid], b = xr[tid + 256];
    float s  = a + b;
    float s2 = a * a + b * b;
#pragma unroll
    for (int off = 16; off; off >>= 1) {
        s  += __shfl_xor_sync(0xffffffffu, s,  off);
        s2 += __shfl_xor_sync(0xffffffffu, s2, off);
    }
    if ((tid & 31) == 0) { redS[tid >> 5] = s; redS2[tid >> 5] = s2; }
    __syncthreads();
    if (tid == 0) {
        float S = 0.f, S2 = 0.f;
#pragma unroll
        for (int w = 0; w < 8; w++) { S += redS[w]; S2 += redS2[w]; }
        redS[0] = S; redS2[0] = S2;
    }
    __syncthreads();
    float mu   = redS[0] * (1.f / 512.f);
    float var  = redS2[0] * (1.f / 512.f) - mu * mu;
    float rstd = rsqrtf(var + 1e-5f);
#pragma unroll
    for (int u = 0; u < 2; u++) {
        int col = tid + u * 256;
        float xv = u ? b : a;
        hr[col] = (xv - mu) * rstd * gam[col] + bet[col] + pr[col];
    }
}

// ---------------- LN2 + residuals ----------------
__global__ void ln2_kernel(const float* __restrict__ o2,
                           const float* __restrict__ r1,
                           const float* __restrict__ x,
                           const float* __restrict__ gam,
                           const float* __restrict__ bet,
                           float* __restrict__ out) {
    __shared__ float redS[8], redS2[8];
    int row = blockIdx.x;
    const float* or_ = o2 + (size_t)row * DM;
    const float* rr  = r1 + (size_t)row * DM;
    const float* xr  = x  + (size_t)row * DM;
    float*       wr  = out + (size_t)row * DM;
    int tid = threadIdx.x;

    float a = or_[tid]       + rr[tid];
    float b = or_[tid + 256] + rr[tid + 256];
    float s  = a + b;
    float s2 = a * a + b * b;
#pragma unroll
    for (int off = 16; off; off >>= 1) {
        s  += __shfl_xor_sync(0xffffffffu, s,  off);
        s2 += __shfl_xor_sync(0xffffffffu, s2, off);
    }
    if ((tid & 31) == 0) { redS[tid >> 5] = s; redS2[tid >> 5] = s2; }
    __syncthreads();
    if (tid == 0) {
        float S = 0.f, S2 = 0.f;
#pragma unroll
        for (int w = 0; w < 8; w++) { S += redS[w]; S2 += redS2[w]; }
        redS[0] = S; redS2[0] = S2;
    }
    __syncthreads();
    float mu   = redS[0] * (1.f / 512.f);
    float var  = redS2[0] * (1.f / 512.f) - mu * mu;
    float rstd = rsqrtf(var + 1e-6f);
#pragma unroll
    for (int u = 0; u < 2; u++) {
        int col = tid + u * 256;
        float vv = u ? b : a;
        wr[col] = (vv - mu) * rstd * gam[col] + bet[col] + xr[col];
    }
}

// ---------------- GEMM: C[8192,512] = A @ W, fp32, 128x128 tile, 8x8/thread ----
#define BK 8
#define ASTR 132

__global__ void __launch_bounds__(256, 2)
gemm512_kernel(const float* __restrict__ A,
               const float* __restrict__ W,
               float* __restrict__ C) {
    __shared__ float As[2][BK][ASTR];   // k-major, transposed A tile
    __shared__ float Ws[2][BK][128];

    int m0 = blockIdx.x * 128;
    int n0 = blockIdx.y * 128;
    int tid = threadIdx.x;
    int tx = tid & 15, ty = tid >> 4;

    int ar = tid >> 1, ak = (tid & 1) * 4;       // A: row 0..127, k 0 or 4
    int wr = tid >> 5, wc = (tid & 31) * 4;      // W: k-row 0..7, col 0..124

    const float* Aptr = A + (size_t)(m0 + ar) * DM + ak;
    const float* Wptr = W + (size_t)wr * DM + n0 + wc;

    float acc[8][8];
#pragma unroll
    for (int i = 0; i < 8; i++)
#pragma unroll
        for (int j = 0; j < 8; j++) acc[i][j] = 0.f;

    // stage 0
    {
        float4 a4 = *(const float4*)Aptr;
        float4 w4 = *(const float4*)Wptr;
        As[0][ak + 0][ar] = a4.x; As[0][ak + 1][ar] = a4.y;
        As[0][ak + 2][ar] = a4.z; As[0][ak + 3][ar] = a4.w;
        *(float4*)&Ws[0][wr][wc] = w4;
    }
    __syncthreads();

    int buf = 0;
#pragma unroll 1
    for (int k0 = 0; k0 < 512; k0 += BK) {
        float4 a4n, w4n;
        bool more = (k0 + BK) < 512;
        if (more) {
            a4n = *(const float4*)(Aptr + k0 + BK);
            w4n = *(const float4*)(Wptr + (size_t)(k0 + BK) * DM);
        }
#pragma unroll
        for (int kk = 0; kk < BK; kk++) {
            float av[8], bv[8];
            *(float4*)(av)     = *(const float4*)&As[buf][kk][ty * 4];
            *(float4*)(av + 4) = *(const float4*)&As[buf][kk][64 + ty * 4];
            *(float4*)(bv)     = *(const float4*)&Ws[buf][kk][tx * 4];
            *(float4*)(bv + 4) = *(const float4*)&Ws[buf][kk][64 + tx * 4];
#pragma unroll
            for (int i = 0; i < 8; i++)
#pragma unroll
                for (int j = 0; j < 8; j++) acc[i][j] += av[i] * bv[j];
        }
        if (more) {
            int nb = buf ^ 1;
            As[nb][ak + 0][ar] = a4n.x; As[nb][ak + 1][ar] = a4n.y;
            As[nb][ak + 2][ar] = a4n.z; As[nb][ak + 3][ar] = a4n.w;
            *(float4*)&Ws[nb][wr][wc] = w4n;
            __syncthreads();
            buf = nb;
        }
    }

#pragma unroll
    for (int i = 0; i < 8; i++) {
        int row = m0 + ((i < 4) ? (ty * 4 + i) : (64 + ty * 4 + i - 4));
        float4 c0 = make_float4(acc[i][0], acc[i][1], acc[i][2], acc[i][3]);
        float4 c1 = make_float4(acc[i][4], acc[i][5], acc[i][6], acc[i][7]);
        *(float4*)(C + (size_t)row * DM + n0 + tx * 4)      = c0;
        *(float4*)(C + (size_t)row * DM + n0 + 64 + tx * 4) = c1;
    }
}

// ---------------- causal flash attention, fp32, 128x64 tiles, 8x4/thread ------
#define QT 128
#define KTILE 64
#define SQS 68
#define SKS 68
#define SPS 68

__global__ void __launch_bounds__(256, 1)
attn_kernel(const float* __restrict__ Q,
            const float* __restrict__ K,
            const float* __restrict__ V,
            float* __restrict__ O) {
    extern __shared__ float sm[];
    float* sQ = sm;                        // 128 x 68
    float* sK = sQ + QT * SQS;             // 64 x 68
    float* sV = sK + KTILE * SKS;          // 64 x 64
    float* sP = sV + KTILE * 64;           // 128 x 68

    int qt = (int)(gridDim.x - 1) - (int)blockIdx.x;   // heavy tiles first
    int bh = blockIdx.y;
    int bb = bh >> 3, hd = bh & 7;
    int tid = threadIdx.x;
    int tx = tid & 15, ty = tid >> 4;
    size_t base = ((size_t)bb * SEQ) * DM + (size_t)hd * DK;

    // Q scale folds in 1/sqrt(64) and log2(e) so softmax uses exp2
    const float qscale = 0.125f * 1.4426950408889634f;

    for (int idx = tid; idx < QT * 16; idx += 256) {
        int r = idx >> 4, c4 = (idx & 15) * 4;
        float4 qv = *(const float4*)(Q + base + (size_t)(qt * QT + r) * DM + c4);
        qv.x *= qscale; qv.y *= qscale; qv.z *= qscale; qv.w *= qscale;
        *(float4*)&sQ[r * SQS + c4] = qv;
    }

    float Oacc[8][4];
    float m_i[8], l_i[8];
#pragma unroll
    for (int i = 0; i < 8; i++) {
        m_i[i] = -1e30f; l_i[i] = 0.f;
#pragma unroll
        for (int j = 0; j < 4; j++) Oacc[i][j] = 0.f;
    }

    int ktmax = 2 * qt + 1;
    for (int kt = 0; kt <= ktmax; kt++) {
        for (int idx = tid; idx < KTILE * 16; idx += 256) {
            int r = idx >> 4, c4 = (idx & 15) * 4;
            size_t ga = base + (size_t)(kt * KTILE + r) * DM + c4;
            *(float4*)&sK[r * SKS + c4] = *(const float4*)(K + ga);
            *(float4*)&sV[r * 64 + c4]  = *(const float4*)(V + ga);
        }
        __syncthreads();

        // S = Q K^T : rows ty+16i, cols tx+16j
        float s[8][4];
#pragma unroll
        for (int i = 0; i < 8; i++)
#pragma unroll
            for (int j = 0; j < 4; j++) s[i][j] = 0.f;

#pragma unroll
        for (int d4 = 0; d4 < 16; d4++) {
            float4 kv[4];
#pragma unroll
            for (int j = 0; j < 4; j++)
                kv[j] = *(const float4*)&sK[(tx + 16 * j) * SKS + d4 * 4];
#pragma unroll
            for (int i = 0; i < 8; i++) {
                float4 qv = *(const float4*)&sQ[(ty + 16 * i) * SQS + d4 * 4];
#pragma unroll
                for (int j = 0; j < 4; j++)
                    s[i][j] += qv.x * kv[j].x + qv.y * kv[j].y +
                               qv.z * kv[j].z + qv.w * kv[j].w;
            }
        }

        if (kt >= 2 * qt) {   // tiles overlapping the diagonal
#pragma unroll
            for (int i = 0; i < 8; i++) {
                int grow = qt * QT + ty + 16 * i;
#pragma unroll
                for (int j = 0; j < 4; j++)
                    if (kt * KTILE + tx + 16 * j > grow) s[i][j] = -1e30f;
            }
        }

        // online softmax (base-2 domain)
#pragma unroll
        for (int i = 0; i < 8; i++) {
            float mt = fmaxf(fmaxf(s[i][0], s[i][1]), fmaxf(s[i][2], s[i][3]));
#pragma unroll
            for (int off = 8; off; off >>= 1)
                mt = fmaxf(mt, __shfl_xor_sync(0xffffffffu, mt, off));
            float mn   = fmaxf(m_i[i], mt);
            float corr = exp2f(m_i[i] - mn);
            m_i[i] = mn;
            float rs = 0.f;
#pragma unroll
            for (int j = 0; j < 4; j++) {
                float p = exp2f(s[i][j] - mn);
                s[i][j] = p;
                rs += p;
            }
#pragma unroll
            for (int off = 8; off; off >>= 1)
                rs += __shfl_xor_sync(0xffffffffu, rs, off);
            l_i[i] = l_i[i] * corr + rs;
#pragma unroll
            for (int j = 0; j < 4; j++) Oacc[i][j] *= corr;
#pragma unroll
            for (int j = 0; j < 4; j++)
                sP[(ty + 16 * i) * SPS + tx + 16 * j] = s[i][j];
        }
        __syncthreads();

        // O += P V : rows ty+16i, dims tx*4+j ; k unrolled by 4 for float4 P
#pragma unroll 4
        for (int k = 0; k < KTILE; k += 4) {
            float4 vv0 = *(const float4*)&sV[(k + 0) * 64 + tx * 4];
            float4 vv1 = *(const float4*)&sV[(k + 1) * 64 + tx * 4];
            float4 vv2 = *(const float4*)&sV[(k + 2) * 64 + tx * 4];
            float4 vv3 = *(const float4*)&sV[(k + 3) * 64 + tx * 4];
#pragma unroll
            for (int i = 0; i < 8; i++) {
                float4 pv = *(const float4*)&sP[(ty + 16 * i) * SPS + k];
                Oacc[i][0] += pv.x * vv0.x + pv.y * vv1.x + pv.z * vv2.x + pv.w * vv3.x;
                Oacc[i][1] += pv.x * vv0.y + pv.y * vv1.y + pv.z * vv2.y + pv.w * vv3.y;
                Oacc[i][2] += pv.x * vv0.z + pv.y * vv1.z + pv.z * vv2.z + pv.w * vv3.z;
                Oacc[i][3] += pv.x * vv0.w + pv.y * vv1.w + pv.z * vv2.w + pv.w * vv3.w;
            }
        }
        __syncthreads();
    }

#pragma unroll
    for (int i = 0; i < 8; i++) {
        float inv = 1.f / l_i[i];
        size_t rowa = base + (size_t)(qt * QT + ty + 16 * i) * DM;
        float4 o4 = make_float4(Oacc[i][0] * inv, Oacc[i][1] * inv,
                                Oacc[i][2] * inv, Oacc[i][3] * inv);
        *(float4*)(O + rowa + tx * 4) = o4;
    }
}

// ---------------- launch ----------------
extern "C" void kernel_launch(void* const* d_in, const int* in_sizes, int n_in,
                              void* d_out, int out_size) {
    const float* x     = (const float*)d_in[0];
    const float* ln1_g = (const float*)d_in[1];
    const float* ln1_b = (const float*)d_in[2];
    const float* wq    = (const float*)d_in[3];
    const float* wk    = (const float*)d_in[4];
    const float* wv    = (const float*)d_in[5];
    const float* wfc   = (const float*)d_in[6];
    const float* ln2_g = (const float*)d_in[7];
    const float* ln2_b = (const float*)d_in[8];
    float* out = (float*)d_out;

    float *ppe, *ph, *pq, *pk, *pv, *po;
    cudaGetSymbolAddress((void**)&ppe, g_pe);
    cudaGetSymbolAddress((void**)&ph,  g_h);
    cudaGetSymbolAddress((void**)&pq,  g_q);
    cudaGetSymbolAddress((void**)&pk,  g_k);
    cudaGetSymbolAddress((void**)&pv,  g_v);
    cudaGetSymbolAddress((void**)&po,  g_o);

    static const int kAttnSmem =
        (QT * SQS + KTILE * SKS + KTILE * 64 + QT * SPS) * 4;
    cudaFuncSetAttribute(attn_kernel,
                         cudaFuncAttributeMaxDynamicSharedMemorySize, kAttnSmem);

    pe_kernel<<<SEQ, 256>>>(ppe);
    ln1_pos_kernel<<<ROWS, 256>>>(x, ln1_g, ln1_b, ppe, ph);

    dim3 gg(ROWS / 128, DM / 128);
    gemm512_kernel<<<gg, 256>>>(ph, wq, pq);
    gemm512_kernel<<<gg, 256>>>(ph, wk, pk);
    gemm512_kernel<<<gg, 256>>>(ph, wv, pv);

    dim3 ga(SEQ / QT, BATCH * NH);
    attn_kernel<<<ga, 256, kAttnSmem>>>(pq, pk, pv, po);

    gemm512_kernel<<<gg, 256>>>(po, wfc, pq);

    ln2_kernel<<<ROWS, 256>>>(pq, ph, x, ln2_g, ln2_b, out);
}

// round 4
// speedup vs baseline: 1.5589x; 1.3025x over previous
#include <cuda_runtime.h>
#include <cuda_bf16.h>
#include <math.h>
#include <stdint.h>

#define BATCH 4
#define SEQ   2048
#define DM    512
#define NH    8
#define DK    64
#define ROWS  (BATCH * SEQ)   // 8192

#if defined(__CUDA_ARCH_FEAT_SM103_ALL) || defined(__CUDA_ARCH_FEAT_SM100_ALL) || \
    defined(__CUDA_ARCH_SPECIFIC__) || defined(__CUDA_ARCH_FAMILY_SPECIFIC__)
#define HAS_TC 1
#else
#define HAS_TC 0
#endif

// ---------------- scratch ----------------
__device__ float g_pe[SEQ * DM];
__device__ float g_h [ROWS * DM];
__device__ float g_q [ROWS * DM];
__device__ float g_k [ROWS * DM];
__device__ float g_v [ROWS * DM];
__device__ __nv_bfloat16 g_ah[ROWS * DM];     // h split hi
__device__ __nv_bfloat16 g_al[ROWS * DM];     // h split lo
__device__ __nv_bfloat16 g_oh[ROWS * DM];     // attn out split hi
__device__ __nv_bfloat16 g_ol[ROWS * DM];     // attn out split lo
__device__ __nv_bfloat16 g_wth[4][DM * DM];   // W^T hi, [n][k] K-major
__device__ __nv_bfloat16 g_wtl[4][DM * DM];   // W^T lo

// ================= helpers =================
__device__ __forceinline__ uint32_t smem_u32(const void* p) {
    uint32_t a;
    asm("{ .reg .u64 t; cvta.to.shared.u64 t, %1; cvt.u32.u64 %0, t; }"
        : "=r"(a) : "l"(p));
    return a;
}

#if HAS_TC
__device__ __forceinline__ uint32_t elect1() {
    uint32_t p;
    asm volatile("{\n\t.reg .pred p;\n\telect.sync _|p, 0xFFFFFFFF;\n\t"
                 "selp.b32 %0, 1, 0, p;\n\t}" : "=r"(p));
    return p;
}
#define TC_ALLOC(smemaddr, ncols) \
    asm volatile("tcgen05.alloc.cta_group::1.sync.aligned.shared::cta.b32 [%0], %1;" \
                 :: "r"(smemaddr), "r"(ncols) : "memory")
#define TC_DEALLOC(tmem, ncols) \
    asm volatile("tcgen05.dealloc.cta_group::1.sync.aligned.b32 %0, %1;" \
                 :: "r"(tmem), "r"(ncols))
#define TC_COMMIT(mbar) \
    asm volatile("tcgen05.commit.cta_group::1.mbarrier::arrive::one.shared::cluster.b64 [%0];" \
                 :: "r"(mbar) : "memory")
#define TC_FENCE_AFTER()  asm volatile("tcgen05.fence::after_thread_sync;" ::: "memory")
#define TC_FENCE_BEFORE() asm volatile("tcgen05.fence::before_thread_sync;" ::: "memory")
#define TC_WAIT_LD()      asm volatile("tcgen05.wait::ld.sync.aligned;" ::: "memory")
#define FENCE_ASYNC_SHARED() asm volatile("fence.proxy.async.shared::cta;" ::: "memory")
#define MBAR_INIT(mbar, cnt) \
    asm volatile("mbarrier.init.shared.b64 [%0], %1;" :: "r"(mbar), "r"(cnt) : "memory")

__device__ __forceinline__ void mbar_wait(uint32_t mbar, uint32_t parity) {
    asm volatile(
        "{\n\t.reg .pred P;\n\t"
        "WL_%=:\n\t"
        "mbarrier.try_wait.parity.acquire.cta.shared::cta.b64 P, [%0], %1, 0x989680;\n\t"
        "@P bra.uni WD_%=;\n\t"
        "bra.uni WL_%=;\n\t"
        "WD_%=:\n\t}"
        :: "r"(mbar), "r"(parity) : "memory");
}

__device__ __forceinline__ void tc_ld_x32(uint32_t* r, uint32_t tmem_addr) {
    asm volatile(
        "tcgen05.ld.sync.aligned.32x32b.x32.b32 "
        "{%0, %1, %2, %3, %4, %5, %6, %7, %8, %9, %10, %11, %12, %13, %14, %15, "
        " %16, %17, %18, %19, %20, %21, %22, %23, %24, %25, %26, %27, %28, %29, %30, %31}, [%32];"
        : "=r"(r[0]),  "=r"(r[1]),  "=r"(r[2]),  "=r"(r[3]),
          "=r"(r[4]),  "=r"(r[5]),  "=r"(r[6]),  "=r"(r[7]),
          "=r"(r[8]),  "=r"(r[9]),  "=r"(r[10]), "=r"(r[11]),
          "=r"(r[12]), "=r"(r[13]), "=r"(r[14]), "=r"(r[15]),
          "=r"(r[16]), "=r"(r[17]), "=r"(r[18]), "=r"(r[19]),
          "=r"(r[20]), "=r"(r[21]), "=r"(r[22]), "=r"(r[23]),
          "=r"(r[24]), "=r"(r[25]), "=r"(r[26]), "=r"(r[27]),
          "=r"(r[28]), "=r"(r[29]), "=r"(r[30]), "=r"(r[31])
        : "r"(tmem_addr));
}

__device__ __forceinline__ void mma_f16_ss(uint32_t d, uint64_t a, uint64_t b,
                                           uint32_t idesc, uint32_t en) {
    asm volatile(
        "{\n\t.reg .pred p;\n\tsetp.ne.u32 p, %4, 0;\n\t"
        "tcgen05.mma.cta_group::1.kind::f16 [%0], %1, %2, %3, {%5, %5, %5, %5}, p;\n\t}"
        :: "r"(d), "l"(a), "l"(b), "r"(idesc), "r"(en), "r"(0u) : "memory");
}

static __device__ __forceinline__ uint64_t make_desc_sw128(uint32_t base) {
    const uint64_t BASE =
        (uint64_t(2) << 61) | (uint64_t(1) << 46) | (uint64_t(64) << 32) | (uint64_t(1) << 16);
    return BASE | ((uint64_t)(base >> 4) & 0x3FFF);
}
#endif  // HAS_TC

// ---------------- positional encoding (fp64) ----------------
__global__ void pe_kernel(float* __restrict__ pe) {
    int t   = blockIdx.x;
    int tid = threadIdx.x;
    const double c = -(9.210340371976184 / 512.0);
#pragma unroll
    for (int u = 0; u < 2; u++) {
        int col = tid + u * 256;
        int i2  = col & ~1;
        double arg = (double)t * exp((double)i2 * c);
        pe[t * DM + col] = (col & 1) ? (float)cos(arg) : (float)sin(arg);
    }
}

// ---------------- W transpose + bf16 split ----------------
__global__ void wsplit_kernel(const float* __restrict__ W,
                              __nv_bfloat16* __restrict__ Th,
                              __nv_bfloat16* __restrict__ Tl) {
    __shared__ float t[32][33];
    int n0 = blockIdx.x * 32, k0 = blockIdx.y * 32;
    int tx = threadIdx.x, ty = threadIdx.y;   // (32, 8)
#pragma unroll
    for (int i = 0; i < 32; i += 8)
        t[ty + i][tx] = W[(size_t)(k0 + ty + i) * DM + n0 + tx];
    __syncthreads();
#pragma unroll
    for (int i = 0; i < 32; i += 8) {
        float v = t[tx][ty + i];
        __nv_bfloat16 h = __float2bfloat16(v);
        __nv_bfloat16 l = __float2bfloat16(v - __bfloat162float(h));
        size_t o = (size_t)(n0 + ty + i) * DM + k0 + tx;
        Th[o] = h; Tl[o] = l;
    }
}

// ---------------- LN1 + pe (+ bf16 split of h) ----------------
__global__ void ln1_pos_kernel(const float* __restrict__ x,
                               const float* __restrict__ gam,
                               const float* __restrict__ bet,
                               const float* __restrict__ pe,
                               float* __restrict__ h,
                               __nv_bfloat16* __restrict__ hh,
                               __nv_bfloat16* __restrict__ hl) {
    __shared__ float redS[8], redS2[8];
    int row = blockIdx.x;
    int t   = row & (SEQ - 1);
    const float* xr = x  + (size_t)row * DM;
    const float* pr = pe + (size_t)t   * DM;
    int tid = threadIdx.x;

    float a = xr[tid], b = xr[tid + 256];
    float s  = a + b;
    float s2 = a * a + b * b;
#pragma unroll
    for (int off = 16; off; off >>= 1) {
        s  += __shfl_xor_sync(0xffffffffu, s,  off);
        s2 += __shfl_xor_sync(0xffffffffu, s2, off);
    }
    if ((tid & 31) == 0) { redS[tid >> 5] = s; redS2[tid >> 5] = s2; }
    __syncthreads();
    if (tid == 0) {
        float S = 0.f, S2 = 0.f;
#pragma unroll
        for (int w = 0; w < 8; w++) { S += redS[w]; S2 += redS2[w]; }
        redS[0] = S; redS2[0] = S2;
    }
    __syncthreads();
    float mu   = redS[0] * (1.f / 512.f);
    float var  = redS2[0] * (1.f / 512.f) - mu * mu;
    float rstd = rsqrtf(var + 1e-5f);
#pragma unroll
    for (int u = 0; u < 2; u++) {
        int col = tid + u * 256;
        float xv = u ? b : a;
        float hv = (xv - mu) * rstd * gam[col] + bet[col] + pr[col];
        size_t o = (size_t)row * DM + col;
        h[o] = hv;
        __nv_bfloat16 hi = __float2bfloat16(hv);
        hh[o] = hi;
        hl[o] = __float2bfloat16(hv - __bfloat162float(hi));
    }
}

// ---------------- LN2 + residuals ----------------
__global__ void ln2_kernel(const float* __restrict__ o2,
                           const float* __restrict__ r1,
                           const float* __restrict__ x,
                           const float* __restrict__ gam,
                           const float* __restrict__ bet,
                           float* __restrict__ out) {
    __shared__ float redS[8], redS2[8];
    int row = blockIdx.x;
    const float* or_ = o2 + (size_t)row * DM;
    const float* rr  = r1 + (size_t)row * DM;
    const float* xr  = x  + (size_t)row * DM;
    float*       wr  = out + (size_t)row * DM;
    int tid = threadIdx.x;

    float a = or_[tid]       + rr[tid];
    float b = or_[tid + 256] + rr[tid + 256];
    float s  = a + b;
    float s2 = a * a + b * b;
#pragma unroll
    for (int off = 16; off; off >>= 1) {
        s  += __shfl_xor_sync(0xffffffffu, s,  off);
        s2 += __shfl_xor_sync(0xffffffffu, s2, off);
    }
    if ((tid & 31) == 0) { redS[tid >> 5] = s; redS2[tid >> 5] = s2; }
    __syncthreads();
    if (tid == 0) {
        float S = 0.f, S2 = 0.f;
#pragma unroll
        for (int w = 0; w < 8; w++) { S += redS[w]; S2 += redS2[w]; }
        redS[0] = S; redS2[0] = S2;
    }
    __syncthreads();
    float mu   = redS[0] * (1.f / 512.f);
    float var  = redS2[0] * (1.f / 512.f) - mu * mu;
    float rstd = rsqrtf(var + 1e-6f);
#pragma unroll
    for (int u = 0; u < 2; u++) {
        int col = tid + u * 256;
        float vv = u ? b : a;
        wr[col] = (vv - mu) * rstd * gam[col] + bet[col] + xr[col];
    }
}

// ================ GEMM: C[M,512] = (Ah+Al) @ (Bh+Bl)^T  (both K-major splits) ==
// tcgen05 path: 128x128 tile, bf16x3, TMEM accumulate.
// fallback path: SIMT 8x8 double-buffered.
#define GIDESC ((1u << 4) | (1u << 7) | (1u << 10) | ((128u / 8) << 17) | ((128u / 16) << 24))
#define GEMM_DSMEM (2 * 65536 + 1024)

__global__ void __launch_bounds__(256, 1)
gemm_tc_kernel(const __nv_bfloat16* __restrict__ Ah,
               const __nv_bfloat16* __restrict__ Al,
               const __nv_bfloat16* __restrict__ Bh,
               const __nv_bfloat16* __restrict__ Bl,
               float* __restrict__ C) {
    extern __shared__ char dsm_raw[];
    uint32_t tid = threadIdx.x, wid = tid >> 5, lid = tid & 31;
    int m0 = blockIdx.x * 128, n0 = blockIdx.y * 128;

#if HAS_TC
    __shared__ __align__(16) uint64_t s_mbar[2];
    __shared__ uint32_t s_tm[1];

    uint32_t raw = smem_u32(dsm_raw);
    uint32_t sb  = (raw + 1023) & ~1023u;
    char* dsm = dsm_raw + (sb - raw);

    uint32_t mb0 = smem_u32(&s_mbar[0]);
    uint32_t mb1 = smem_u32(&s_mbar[1]);

    if (wid == 0) TC_ALLOC(smem_u32(s_tm), 128);
    if (tid == 0) { MBAR_INIT(mb0, 1); MBAR_INIT(mb1, 1); }
    __syncthreads();
    uint32_t tmem = s_tm[0];

    const uint32_t OFF_AH = 0, OFF_AL = 16384, OFF_BH = 32768, OFF_BL = 49152;
    int ph0 = 0, ph1 = 0;
    uint32_t first = 1;

    // per-thread copy role: idx in [0, 1024) covers one 128x64 bf16 tile as
    // 128 rows x 8 sixteen-byte groups. 256 threads x 4 iters.
#pragma unroll 1
    for (int c = 0; c < 8; c++) {
        int buf = c & 1;
        uint32_t boff = (uint32_t)buf * 65536u;
        if (c >= 2) {
            if (buf == 0) { mbar_wait(mb0, ph0); ph0 ^= 1; }
            else          { mbar_wait(mb1, ph1); ph1 ^= 1; }
        }
        int k0 = c * 64;

#pragma unroll
        for (int i = 0; i < 4; i++) {
            int idx = i * 256 + (int)tid;
            int r = idx >> 3, g = idx & 7;
            uint32_t o  = (uint32_t)(r * 128 + g * 16);
            uint32_t so = o ^ ((o >> 3) & 0x70);
            size_t ga = (size_t)(m0 + r) * DM + k0 + g * 8;
            size_t gb = (size_t)(n0 + r) * DM + k0 + g * 8;
            *(uint4*)(dsm + boff + OFF_AH + so) = *(const uint4*)(Ah + ga);
            *(uint4*)(dsm + boff + OFF_AL + so) = *(const uint4*)(Al + ga);
            *(uint4*)(dsm + boff + OFF_BH + so) = *(const uint4*)(Bh + gb);
            *(uint4*)(dsm + boff + OFF_BL + so) = *(const uint4*)(Bl + gb);
        }
        __syncthreads();

        if (wid == 0 && elect1()) {
            FENCE_ASYNC_SHARED();
            uint64_t dah = make_desc_sw128(sb + boff + OFF_AH);
            uint64_t dal = make_desc_sw128(sb + boff + OFF_AL);
            uint64_t dbh = make_desc_sw128(sb + boff + OFF_BH);
            uint64_t dbl = make_desc_sw128(sb + boff + OFF_BL);
#pragma unroll
            for (int ks = 0; ks < 4; ks++) {
                mma_f16_ss(tmem, dah + ks * 2, dbh + ks * 2, GIDESC, first ? 0u : 1u);
                first = 0;
                mma_f16_ss(tmem, dah + ks * 2, dbl + ks * 2, GIDESC, 1u);
                mma_f16_ss(tmem, dal + ks * 2, dbh + ks * 2, GIDESC, 1u);
            }
            TC_COMMIT(buf == 0 ? mb0 : mb1);
        }
    }

    mbar_wait(mb1, (uint32_t)ph1);
    TC_FENCE_AFTER();

    int sub  = wid & 3;
    int colb = (wid >> 2) * 64;
    int row  = m0 + sub * 32 + (int)lid;
    float* Cr = C + (size_t)row * DM + n0 + colb;

    uint32_t d0[32], d1[32];
    tc_ld_x32(d0, tmem + colb);
    tc_ld_x32(d1, tmem + colb + 32);
    TC_WAIT_LD();
#pragma unroll
    for (int j = 0; j < 8; j++)
        *(float4*)(Cr + j * 4) = make_float4(
            __uint_as_float(d0[4*j]),   __uint_as_float(d0[4*j+1]),
            __uint_as_float(d0[4*j+2]), __uint_as_float(d0[4*j+3]));
#pragma unroll
    for (int j = 0; j < 8; j++)
        *(float4*)(Cr + 32 + j * 4) = make_float4(
            __uint_as_float(d1[4*j]),   __uint_as_float(d1[4*j+1]),
            __uint_as_float(d1[4*j+2]), __uint_as_float(d1[4*j+3]));
    TC_FENCE_BEFORE();
    __syncthreads();
    if (wid == 0) TC_DEALLOC(tmem, 128);

#else   // ---------------- SIMT fallback (generic pass) ----------------
    float* As = (float*)dsm_raw;            // [2][8][132]
    float* Ws = As + 2 * 8 * 132;           // [2][8][128]
    int tx = tid & 15, ty = (int)(tid >> 4);

    int r = tid & 127;
    bool isA = tid < 128;
    const __nv_bfloat16* Ph = isA ? Ah + (size_t)(m0 + r) * DM
                                  : Bh + (size_t)(n0 + r) * DM;
    const __nv_bfloat16* Pl = isA ? Al + (size_t)(m0 + r) * DM
                                  : Bl + (size_t)(n0 + r) * DM;
    int stride = isA ? 132 : 128;

    float acc[8][8];
#pragma unroll
    for (int i = 0; i < 8; i++)
#pragma unroll
        for (int j = 0; j < 8; j++) acc[i][j] = 0.f;

    auto stage = [&](int buf, int k0) {
        uint4 vh = *(const uint4*)(Ph + k0);
        uint4 vl = *(const uint4*)(Pl + k0);
        const __nv_bfloat16* bh = (const __nv_bfloat16*)&vh;
        const __nv_bfloat16* bl = (const __nv_bfloat16*)&vl;
        float* dst = (isA ? As + buf * 8 * 132 : Ws + buf * 8 * 128) + r;
#pragma unroll
        for (int k = 0; k < 8; k++)
            dst[k * stride] = __bfloat162float(bh[k]) + __bfloat162float(bl[k]);
    };

    stage(0, 0);
    __syncthreads();
    int buf = 0;
#pragma unroll 1
    for (int k0 = 0; k0 < 512; k0 += 8) {
        if (k0 + 8 < 512) stage(buf ^ 1, k0 + 8);
#pragma unroll
        for (int kk = 0; kk < 8; kk++) {
            float av[8], bv[8];
            const float* ar = As + buf * 8 * 132 + kk * 132;
            const float* wr = Ws + buf * 8 * 128 + kk * 128;
            *(float4*)(av)     = *(const float4*)(ar + ty * 4);
            *(float4*)(av + 4) = *(const float4*)(ar + 64 + ty * 4);
            *(float4*)(bv)     = *(const float4*)(wr + tx * 4);
            *(float4*)(bv + 4) = *(const float4*)(wr + 64 + tx * 4);
#pragma unroll
            for (int i = 0; i < 8; i++)
#pragma unroll
                for (int j = 0; j < 8; j++) acc[i][j] += av[i] * bv[j];
        }
        __syncthreads();
        buf ^= 1;
    }

#pragma unroll
    for (int i = 0; i < 8; i++) {
        int row = m0 + ((i < 4) ? (ty * 4 + i) : (64 + ty * 4 + i - 4));
        *(float4*)(C + (size_t)row * DM + n0 + tx * 4) =
            make_float4(acc[i][0], acc[i][1], acc[i][2], acc[i][3]);
        *(float4*)(C + (size_t)row * DM + n0 + 64 + tx * 4) =
            make_float4(acc[i][4], acc[i][5], acc[i][6], acc[i][7]);
    }
#endif
}

// ---------------- causal flash attention, fp32, 128x64 tiles, 8x4/thread ------
#define QT 128
#define KTILE 64
#define SQS 68
#define SKS 68
#define SPS 68

__global__ void __launch_bounds__(256, 1)
attn_kernel(const float* __restrict__ Q,
            const float* __restrict__ K,
            const float* __restrict__ V,
            __nv_bfloat16* __restrict__ Oh,
            __nv_bfloat16* __restrict__ Ol) {
    extern __shared__ float sm[];
    float* sQ = sm;
    float* sK = sQ + QT * SQS;
    float* sV = sK + KTILE * SKS;
    float* sP = sV + KTILE * 64;

    int qt = (int)(gridDim.x - 1) - (int)blockIdx.x;
    int bh = blockIdx.y;
    int bb = bh >> 3, hd = bh & 7;
    int tid = threadIdx.x;
    int tx = tid & 15, ty = tid >> 4;
    size_t base = ((size_t)bb * SEQ) * DM + (size_t)hd * DK;

    const float qscale = 0.125f * 1.4426950408889634f;

    for (int idx = tid; idx < QT * 16; idx += 256) {
        int r = idx >> 4, c4 = (idx & 15) * 4;
        float4 qv = *(const float4*)(Q + base + (size_t)(qt * QT + r) * DM + c4);
        qv.x *= qscale; qv.y *= qscale; qv.z *= qscale; qv.w *= qscale;
        *(float4*)&sQ[r * SQS + c4] = qv;
    }

    float Oacc[8][4];
    float m_i[8], l_i[8];
#pragma unroll
    for (int i = 0; i < 8; i++) {
        m_i[i] = -1e30f; l_i[i] = 0.f;
#pragma unroll
        for (int j = 0; j < 4; j++) Oacc[i][j] = 0.f;
    }

    int ktmax = 2 * qt + 1;
    for (int kt = 0; kt <= ktmax; kt++) {
        for (int idx = tid; idx < KTILE * 16; idx += 256) {
            int r = idx >> 4, c4 = (idx & 15) * 4;
            size_t ga = base + (size_t)(kt * KTILE + r) * DM + c4;
            *(float4*)&sK[r * SKS + c4] = *(const float4*)(K + ga);
            *(float4*)&sV[r * 64 + c4]  = *(const float4*)(V + ga);
        }
        __syncthreads();

        float s[8][4];
#pragma unroll
        for (int i = 0; i < 8; i++)
#pragma unroll
            for (int j = 0; j < 4; j++) s[i][j] = 0.f;

#pragma unroll
        for (int d4 = 0; d4 < 16; d4++) {
            float4 kv[4];
#pragma unroll
            for (int j = 0; j < 4; j++)
                kv[j] = *(const float4*)&sK[(tx + 16 * j) * SKS + d4 * 4];
#pragma unroll
            for (int i = 0; i < 8; i++) {
                float4 qv = *(const float4*)&sQ[(ty + 16 * i) * SQS + d4 * 4];
#pragma unroll
                for (int j = 0; j < 4; j++)
                    s[i][j] += qv.x * kv[j].x + qv.y * kv[j].y +
                               qv.z * kv[j].z + qv.w * kv[j].w;
            }
        }

        if (kt >= 2 * qt) {
#pragma unroll
            for (int i = 0; i < 8; i++) {
                int grow = qt * QT + ty + 16 * i;
#pragma unroll
                for (int j = 0; j < 4; j++)
                    if (kt * KTILE + tx + 16 * j > grow) s[i][j] = -1e30f;
            }
        }

#pragma unroll
        for (int i = 0; i < 8; i++) {
            float mt = fmaxf(fmaxf(s[i][0], s[i][1]), fmaxf(s[i][2], s[i][3]));
#pragma unroll
            for (int off = 8; off; off >>= 1)
                mt = fmaxf(mt, __shfl_xor_sync(0xffffffffu, mt, off));
            float mn   = fmaxf(m_i[i], mt);
            float corr = exp2f(m_i[i] - mn);
            m_i[i] = mn;
            float rs = 0.f;
#pragma unroll
            for (int j = 0; j < 4; j++) {
                float p = exp2f(s[i][j] - mn);
                s[i][j] = p;
                rs += p;
            }
#pragma unroll
            for (int off = 8; off; off >>= 1)
                rs += __shfl_xor_sync(0xffffffffu, rs, off);
            l_i[i] = l_i[i] * corr + rs;
#pragma unroll
            for (int j = 0; j < 4; j++) Oacc[i][j] *= corr;
#pragma unroll
            for (int j = 0; j < 4; j++)
                sP[(ty + 16 * i) * SPS + tx + 16 * j] = s[i][j];
        }
        __syncthreads();

#pragma unroll 4
        for (int k = 0; k < KTILE; k += 4) {
            float4 vv0 = *(const float4*)&sV[(k + 0) * 64 + tx * 4];
            float4 vv1 = *(const float4*)&sV[(k + 1) * 64 + tx * 4];
            float4 vv2 = *(const float4*)&sV[(k + 2) * 64 + tx * 4];
            float4 vv3 = *(const float4*)&sV[(k + 3) * 64 + tx * 4];
#pragma unroll
            for (int i = 0; i < 8; i++) {
                float4 pv = *(const float4*)&sP[(ty + 16 * i) * SPS + k];
                Oacc[i][0] += pv.x * vv0.x + pv.y * vv1.x + pv.z * vv2.x + pv.w * vv3.x;
                Oacc[i][1] += pv.x * vv0.y + pv.y * vv1.y + pv.z * vv2.y + pv.w * vv3.y;
                Oacc[i][2] += pv.x * vv0.z + pv.y * vv1.z + pv.z * vv2.z + pv.w * vv3.z;
                Oacc[i][3] += pv.x * vv0.w + pv.y * vv1.w + pv.z * vv2.w + pv.w * vv3.w;
            }
        }
        __syncthreads();
    }

    // epilogue: normalize + bf16 hi/lo split store
#pragma unroll
    for (int i = 0; i < 8; i++) {
        float inv = 1.f / l_i[i];
        size_t rowa = base + (size_t)(qt * QT + ty + 16 * i) * DM + tx * 4;
        ushort4 hh, ll;
        float v0 = Oacc[i][0] * inv, v1 = Oacc[i][1] * inv,
              v2 = Oacc[i][2] * inv, v3 = Oacc[i][3] * inv;
        __nv_bfloat16 h0 = __float2bfloat16(v0), h1 = __float2bfloat16(v1),
                      h2 = __float2bfloat16(v2), h3 = __float2bfloat16(v3);
        hh.x = __bfloat16_as_ushort(h0); hh.y = __bfloat16_as_ushort(h1);
        hh.z = __bfloat16_as_ushort(h2); hh.w = __bfloat16_as_ushort(h3);
        ll.x = __bfloat16_as_ushort(__float2bfloat16(v0 - __bfloat162float(h0)));
        ll.y = __bfloat16_as_ushort(__float2bfloat16(v1 - __bfloat162float(h1)));
        ll.z = __bfloat16_as_ushort(__float2bfloat16(v2 - __bfloat162float(h2)));
        ll.w = __bfloat16_as_ushort(__float2bfloat16(v3 - __bfloat162float(h3)));
        *(ushort4*)(Oh + rowa) = hh;
        *(ushort4*)(Ol + rowa) = ll;
    }
}

// ---------------- launch ----------------
extern "C" void kernel_launch(void* const* d_in, const int* in_sizes, int n_in,
                              void* d_out, int out_size) {
    const float* x     = (const float*)d_in[0];
    const float* ln1_g = (const float*)d_in[1];
    const float* ln1_b = (const float*)d_in[2];
    const float* wq    = (const float*)d_in[3];
    const float* wk    = (const float*)d_in[4];
    const float* wv    = (const float*)d_in[5];
    const float* wfc   = (const float*)d_in[6];
    const float* ln2_g = (const float*)d_in[7];
    const float* ln2_b = (const float*)d_in[8];
    float* out = (float*)d_out;

    float *ppe, *ph, *pq, *pk, *pv;
    __nv_bfloat16 *pwh, *pwl, *pah, *pal, *poh, *pol;
    cudaGetSymbolAddress((void**)&ppe, g_pe);
    cudaGetSymbolAddress((void**)&ph,  g_h);
    cudaGetSymbolAddress((void**)&pq,  g_q);
    cudaGetSymbolAddress((void**)&pk,  g_k);
    cudaGetSymbolAddress((void**)&pv,  g_v);
    cudaGetSymbolAddress((void**)&pwh, g_wth);
    cudaGetSymbolAddress((void**)&pwl, g_wtl);
    cudaGetSymbolAddress((void**)&pah, g_ah);
    cudaGetSymbolAddress((void**)&pal, g_al);
    cudaGetSymbolAddress((void**)&poh, g_oh);
    cudaGetSymbolAddress((void**)&pol, g_ol);

    static const int kAttnSmem =
        (QT * SQS + KTILE * SKS + KTILE * 64 + QT * SPS) * 4;
    cudaFuncSetAttribute(attn_kernel,
                         cudaFuncAttributeMaxDynamicSharedMemorySize, kAttnSmem);
    cudaFuncSetAttribute(gemm_tc_kernel,
                         cudaFuncAttributeMaxDynamicSharedMemorySize, GEMM_DSMEM);

    pe_kernel<<<SEQ, 256>>>(ppe);

    dim3 wt(32, 8);
    dim3 wgrid(16, 16);
    const float* ws[4] = {wq, wk, wv, wfc};
    for (int i = 0; i < 4; i++)
        wsplit_kernel<<<wgrid, wt>>>(ws[i], pwh + (size_t)i * DM * DM,
                                            pwl + (size_t)i * DM * DM);

    ln1_pos_kernel<<<ROWS, 256>>>(x, ln1_g, ln1_b, ppe, ph, pah, pal);

    dim3 gg(ROWS / 128, DM / 128);
    gemm_tc_kernel<<<gg, 256, GEMM_DSMEM>>>(pah, pal, pwh + 0 * (size_t)DM * DM, pwl + 0 * (size_t)DM * DM, pq);
    gemm_tc_kernel<<<gg, 256, GEMM_DSMEM>>>(pah, pal, pwh + 1 * (size_t)DM * DM, pwl + 1 * (size_t)DM * DM, pk);
    gemm_tc_kernel<<<gg, 256, GEMM_DSMEM>>>(pah, pal, pwh + 2 * (size_t)DM * DM, pwl + 2 * (size_t)DM * DM, pv);

    dim3 ga(SEQ / QT, BATCH * NH);
    attn_kernel<<<ga, 256, kAttnSmem>>>(pq, pk, pv, poh, pol);

    gemm_tc_kernel<<<gg, 256, GEMM_DSMEM>>>(poh, pol, pwh + 3 * (size_t)DM * DM, pwl + 3 * (size_t)DM * DM, pq);

    ln2_kernel<<<ROWS, 256>>>(pq, ph, x, ln2_g, ln2_b, out);
}

// round 5
// speedup vs baseline: 2.9426x; 1.8876x over previous
#include <cuda_runtime.h>
#include <cuda_bf16.h>
#include <math.h>
#include <stdint.h>

#define BATCH 4
#define SEQ   2048
#define DM    512
#define NH    8
#define DK    64
#define ROWS  (BATCH * SEQ)   // 8192

#if defined(__CUDA_ARCH_FEAT_SM103_ALL) || defined(__CUDA_ARCH_FEAT_SM100_ALL) || \
    defined(__CUDA_ARCH_SPECIFIC__) || defined(__CUDA_ARCH_FAMILY_SPECIFIC__)
#define HAS_TC 1
#else
#define HAS_TC 0
#endif

// ---------------- scratch ----------------
__device__ float g_pe[SEQ * DM];
__device__ float g_h [ROWS * DM];            // residual1 (fp32)
__device__ float g_v [ROWS * DM];            // v proj fp32; reused as fc output
__device__ __nv_bfloat16 g_ah[ROWS * DM];    // h split hi
__device__ __nv_bfloat16 g_al[ROWS * DM];
__device__ __nv_bfloat16 g_qh[ROWS * DM];    // q (pre-scaled) splits
__device__ __nv_bfloat16 g_ql[ROWS * DM];
__device__ __nv_bfloat16 g_kh[ROWS * DM];
__device__ __nv_bfloat16 g_kl[ROWS * DM];
__device__ __nv_bfloat16 g_oh[ROWS * DM];    // attn out splits
__device__ __nv_bfloat16 g_ol[ROWS * DM];
__device__ __nv_bfloat16 g_vth[BATCH * NH * DK * SEQ];  // [bh][dim][key]
__device__ __nv_bfloat16 g_vtl[BATCH * NH * DK * SEQ];
__device__ __nv_bfloat16 g_wth[4][DM * DM];  // W^T hi, [n][k]
__device__ __nv_bfloat16 g_wtl[4][DM * DM];

// ================= helpers =================
__device__ __forceinline__ uint32_t smem_u32(const void* p) {
    uint32_t a;
    asm("{ .reg .u64 t; cvta.to.shared.u64 t, %1; cvt.u32.u64 %0, t; }"
        : "=r"(a) : "l"(p));
    return a;
}

__device__ __forceinline__ float fast_exp2(float x) {
    x = fminf(fmaxf(x, -120.f), 120.f);
    int   ii = __float2int_rn(x);
    float f  = x - (float)ii;                 // |f| <= 0.5
    float p  = 1.5403530394e-4f;              // 2^f Taylor deg-6, err ~1e-7
    p = fmaf(p, f, 1.3333558146e-3f);
    p = fmaf(p, f, 9.6181291076e-3f);
    p = fmaf(p, f, 5.5504108665e-2f);
    p = fmaf(p, f, 2.4022650696e-1f);
    p = fmaf(p, f, 6.9314718056e-1f);
    p = fmaf(p, f, 1.0f);
    return p * __int_as_float((ii + 127) << 23);
}

#if HAS_TC
__device__ __forceinline__ uint32_t elect1() {
    uint32_t p;
    asm volatile("{\n\t.reg .pred p;\n\telect.sync _|p, 0xFFFFFFFF;\n\t"
                 "selp.b32 %0, 1, 0, p;\n\t}" : "=r"(p));
    return p;
}
#define TC_ALLOC(smemaddr, ncols) \
    asm volatile("tcgen05.alloc.cta_group::1.sync.aligned.shared::cta.b32 [%0], %1;" \
                 :: "r"(smemaddr), "r"(ncols) : "memory")
#define TC_DEALLOC(tmem, ncols) \
    asm volatile("tcgen05.dealloc.cta_group::1.sync.aligned.b32 %0, %1;" \
                 :: "r"(tmem), "r"(ncols))
#define TC_COMMIT(mbar) \
    asm volatile("tcgen05.commit.cta_group::1.mbarrier::arrive::one.shared::cluster.b64 [%0];" \
                 :: "r"(mbar) : "memory")
#define TC_FENCE_AFTER()  asm volatile("tcgen05.fence::after_thread_sync;" ::: "memory")
#define TC_FENCE_BEFORE() asm volatile("tcgen05.fence::before_thread_sync;" ::: "memory")
#define TC_WAIT_LD()      asm volatile("tcgen05.wait::ld.sync.aligned;" ::: "memory")
#define FENCE_ASYNC_SHARED() asm volatile("fence.proxy.async.shared::cta;" ::: "memory")
#define MBAR_INIT(mbar, cnt) \
    asm volatile("mbarrier.init.shared.b64 [%0], %1;" :: "r"(mbar), "r"(cnt) : "memory")

__device__ __forceinline__ void mbar_wait(uint32_t mbar, uint32_t parity) {
    asm volatile(
        "{\n\t.reg .pred P;\n\t"
        "WL_%=:\n\t"
        "mbarrier.try_wait.parity.acquire.cta.shared::cta.b64 P, [%0], %1, 0x989680;\n\t"
        "@P bra.uni WD_%=;\n\t"
        "bra.uni WL_%=;\n\t"
        "WD_%=:\n\t}"
        :: "r"(mbar), "r"(parity) : "memory");
}

__device__ __forceinline__ void tc_ld_x32(uint32_t* r, uint32_t tmem_addr) {
    asm volatile(
        "tcgen05.ld.sync.aligned.32x32b.x32.b32 "
        "{%0, %1, %2, %3, %4, %5, %6, %7, %8, %9, %10, %11, %12, %13, %14, %15, "
        " %16, %17, %18, %19, %20, %21, %22, %23, %24, %25, %26, %27, %28, %29, %30, %31}, [%32];"
        : "=r"(r[0]),  "=r"(r[1]),  "=r"(r[2]),  "=r"(r[3]),
          "=r"(r[4]),  "=r"(r[5]),  "=r"(r[6]),  "=r"(r[7]),
          "=r"(r[8]),  "=r"(r[9]),  "=r"(r[10]), "=r"(r[11]),
          "=r"(r[12]), "=r"(r[13]), "=r"(r[14]), "=r"(r[15]),
          "=r"(r[16]), "=r"(r[17]), "=r"(r[18]), "=r"(r[19]),
          "=r"(r[20]), "=r"(r[21]), "=r"(r[22]), "=r"(r[23]),
          "=r"(r[24]), "=r"(r[25]), "=r"(r[26]), "=r"(r[27]),
          "=r"(r[28]), "=r"(r[29]), "=r"(r[30]), "=r"(r[31])
        : "r"(tmem_addr));
}

__device__ __forceinline__ void mma_f16_ss(uint32_t d, uint64_t a, uint64_t b,
                                           uint32_t idesc, uint32_t en) {
    asm volatile(
        "{\n\t.reg .pred p;\n\tsetp.ne.u32 p, %4, 0;\n\t"
        "tcgen05.mma.cta_group::1.kind::f16 [%0], %1, %2, %3, {%5, %5, %5, %5}, p;\n\t}"
        :: "r"(d), "l"(a), "l"(b), "r"(idesc), "r"(en), "r"(0u) : "memory");
}

static __device__ __forceinline__ uint64_t make_desc_sw128(uint32_t base) {
    const uint64_t BASE =
        (uint64_t(2) << 61) | (uint64_t(1) << 46) | (uint64_t(64) << 32) | (uint64_t(1) << 16);
    return BASE | ((uint64_t)(base >> 4) & 0x3FFF);
}
#endif  // HAS_TC

// ---------------- positional encoding (fp64) ----------------
__global__ void pe_kernel(float* __restrict__ pe) {
    int t   = blockIdx.x;
    int tid = threadIdx.x;
    const double c = -(9.210340371976184 / 512.0);
#pragma unroll
    for (int u = 0; u < 2; u++) {
        int col = tid + u * 256;
        int i2  = col & ~1;
        double arg = (double)t * exp((double)i2 * c);
        pe[t * DM + col] = (col & 1) ? (float)cos(arg) : (float)sin(arg);
    }
}

// ---------------- W transpose + bf16 split ----------------
__global__ void wsplit_kernel(const float* __restrict__ W,
                              __nv_bfloat16* __restrict__ Th,
                              __nv_bfloat16* __restrict__ Tl) {
    __shared__ float t[32][33];
    int n0 = blockIdx.x * 32, k0 = blockIdx.y * 32;
    int tx = threadIdx.x, ty = threadIdx.y;
#pragma unroll
    for (int i = 0; i < 32; i += 8)
        t[ty + i][tx] = W[(size_t)(k0 + ty + i) * DM + n0 + tx];
    __syncthreads();
#pragma unroll
    for (int i = 0; i < 32; i += 8) {
        float v = t[tx][ty + i];
        __nv_bfloat16 h = __float2bfloat16(v);
        __nv_bfloat16 l = __float2bfloat16(v - __bfloat162float(h));
        size_t o = (size_t)(n0 + ty + i) * DM + k0 + tx;
        Th[o] = h; Tl[o] = l;
    }
}

// ---------------- V transpose + split: [row][dim] -> [bh][dim][key] ----------------
__global__ void vtrans_kernel(const float* __restrict__ V,
                              __nv_bfloat16* __restrict__ Vth,
                              __nv_bfloat16* __restrict__ Vtl) {
    __shared__ float t[64][65];
    int kt = blockIdx.x, bh = blockIdx.y;
    int bb = bh >> 3, hd = bh & 7;
    int tid = threadIdx.x;
    const float* src = V + ((size_t)bb * SEQ + (size_t)kt * 64) * DM + hd * 64;
#pragma unroll
    for (int i = 0; i < 16; i++) {
        int idx = i * 256 + tid;
        int k = idx >> 6, d = idx & 63;
        t[k][d] = src[(size_t)k * DM + d];
    }
    __syncthreads();
    size_t ob = ((size_t)bh * 64) * SEQ + (size_t)kt * 64;
#pragma unroll
    for (int i = 0; i < 16; i++) {
        int idx = i * 256 + tid;
        int d = idx >> 6, k = idx & 63;
        float v = t[k][d];
        __nv_bfloat16 h = __float2bfloat16(v);
        size_t o = ob + (size_t)d * SEQ + k;
        Vth[o] = h;
        Vtl[o] = __float2bfloat16(v - __bfloat162float(h));
    }
}

// ---------------- LN1 + pe (+ bf16 split of h) ----------------
__global__ void ln1_pos_kernel(const float* __restrict__ x,
                               const float* __restrict__ gam,
                               const float* __restrict__ bet,
                               const float* __restrict__ pe,
                               float* __restrict__ h,
                               __nv_bfloat16* __restrict__ hh,
                               __nv_bfloat16* __restrict__ hl) {
    __shared__ float redS[8], redS2[8];
    int row = blockIdx.x;
    int t   = row & (SEQ - 1);
    const float* xr = x  + (size_t)row * DM;
    const float* pr = pe + (size_t)t   * DM;
    int tid = threadIdx.x;

    float a = xr[tid], b = xr[tid + 256];
    float s  = a + b;
    float s2 = a * a + b * b;
#pragma unroll
    for (int off = 16; off; off >>= 1) {
        s  += __shfl_xor_sync(0xffffffffu, s,  off);
        s2 += __shfl_xor_sync(0xffffffffu, s2, off);
    }
    if ((tid & 31) == 0) { redS[tid >> 5] = s; redS2[tid >> 5] = s2; }
    __syncthreads();
    if (tid == 0) {
        float S = 0.f, S2 = 0.f;
#pragma unroll
        for (int w = 0; w < 8; w++) { S += redS[w]; S2 += redS2[w]; }
        redS[0] = S; redS2[0] = S2;
    }
    __syncthreads();
    float mu   = redS[0] * (1.f / 512.f);
    float var  = redS2[0] * (1.f / 512.f) - mu * mu;
    float rstd = rsqrtf(var + 1e-5f);
#pragma unroll
    for (int u = 0; u < 2; u++) {
        int col = tid + u * 256;
        float xv = u ? b : a;
        float hv = (xv - mu) * rstd * gam[col] + bet[col] + pr[col];
        size_t o = (size_t)row * DM + col;
        h[o] = hv;
        __nv_bfloat16 hi = __float2bfloat16(hv);
        hh[o] = hi;
        hl[o] = __float2bfloat16(hv - __bfloat162float(hi));
    }
}

// ---------------- LN2 + residuals ----------------
__global__ void ln2_kernel(const float* __restrict__ o2,
                           const float* __restrict__ r1,
                           const float* __restrict__ x,
                           const float* __restrict__ gam,
                           const float* __restrict__ bet,
                           float* __restrict__ out) {
    __shared__ float redS[8], redS2[8];
    int row = blockIdx.x;
    const float* or_ = o2 + (size_t)row * DM;
    const float* rr  = r1 + (size_t)row * DM;
    const float* xr  = x  + (size_t)row * DM;
    float*       wr  = out + (size_t)row * DM;
    int tid = threadIdx.x;

    float a = or_[tid]       + rr[tid];
    float b = or_[tid + 256] + rr[tid + 256];
    float s  = a + b;
    float s2 = a * a + b * b;
#pragma unroll
    for (int off = 16; off; off >>= 1) {
        s  += __shfl_xor_sync(0xffffffffu, s,  off);
        s2 += __shfl_xor_sync(0xffffffffu, s2, off);
    }
    if ((tid & 31) == 0) { redS[tid >> 5] = s; redS2[tid >> 5] = s2; }
    __syncthreads();
    if (tid == 0) {
        float S = 0.f, S2 = 0.f;
#pragma unroll
        for (int w = 0; w < 8; w++) { S += redS[w]; S2 += redS2[w]; }
        redS[0] = S; redS2[0] = S2;
    }
    __syncthreads();
    float mu   = redS[0] * (1.f / 512.f);
    float var  = redS2[0] * (1.f / 512.f) - mu * mu;
    float rstd = rsqrtf(var + 1e-6f);
#pragma unroll
    for (int u = 0; u < 2; u++) {
        int col = tid + u * 256;
        float vv = u ? b : a;
        wr[col] = (vv - mu) * rstd * gam[col] + bet[col] + xr[col];
    }
}

// ================ GEMM (bf16x3): mode 0 -> fp32 C; mode 1 -> scaled bf16 splits ==
#define GIDESC ((1u << 4) | (1u << 7) | (1u << 10) | ((128u / 8) << 17) | ((128u / 16) << 24))
#define GEMM_DSMEM (2 * 65536 + 1024)

__global__ void __launch_bounds__(256, 1)
gemm_tc_kernel(const __nv_bfloat16* __restrict__ Ah,
               const __nv_bfloat16* __restrict__ Al,
               const __nv_bfloat16* __restrict__ Bh,
               const __nv_bfloat16* __restrict__ Bl,
               float* __restrict__ C,
               __nv_bfloat16* __restrict__ Ch,
               __nv_bfloat16* __restrict__ Cl,
               float scale, int mode) {
    extern __shared__ char dsm_raw[];
    uint32_t tid = threadIdx.x, wid = tid >> 5, lid = tid & 31;
    int m0 = blockIdx.x * 128, n0 = blockIdx.y * 128;

#if HAS_TC
    __shared__ __align__(16) uint64_t s_mbar[2];
    __shared__ uint32_t s_tm[1];

    uint32_t raw = smem_u32(dsm_raw);
    uint32_t sb  = (raw + 1023) & ~1023u;
    char* dsm = dsm_raw + (sb - raw);

    uint32_t mb0 = smem_u32(&s_mbar[0]);
    uint32_t mb1 = smem_u32(&s_mbar[1]);

    if (wid == 0) TC_ALLOC(smem_u32(s_tm), 128);
    if (tid == 0) { MBAR_INIT(mb0, 1); MBAR_INIT(mb1, 1); }
    __syncthreads();
    uint32_t tmem = s_tm[0];

    const uint32_t OFF_AH = 0, OFF_AL = 16384, OFF_BH = 32768, OFF_BL = 49152;
    int ph0 = 0, ph1 = 0;
    uint32_t first = 1;

#pragma unroll 1
    for (int c = 0; c < 8; c++) {
        int buf = c & 1;
        uint32_t boff = (uint32_t)buf * 65536u;
        if (c >= 2) {
            if (buf == 0) { mbar_wait(mb0, ph0); ph0 ^= 1; }
            else          { mbar_wait(mb1, ph1); ph1 ^= 1; }
        }
        int k0 = c * 64;

#pragma unroll
        for (int i = 0; i < 4; i++) {
            int idx = i * 256 + (int)tid;
            int r = idx >> 3, g = idx & 7;
            uint32_t o  = (uint32_t)(r * 128 + g * 16);
            uint32_t so = o ^ ((o >> 3) & 0x70);
            size_t ga = (size_t)(m0 + r) * DM + k0 + g * 8;
            size_t gb = (size_t)(n0 + r) * DM + k0 + g * 8;
            *(uint4*)(dsm + boff + OFF_AH + so) = *(const uint4*)(Ah + ga);
            *(uint4*)(dsm + boff + OFF_AL + so) = *(const uint4*)(Al + ga);
            *(uint4*)(dsm + boff + OFF_BH + so) = *(const uint4*)(Bh + gb);
            *(uint4*)(dsm + boff + OFF_BL + so) = *(const uint4*)(Bl + gb);
        }
        __syncthreads();

        if (wid == 0 && elect1()) {
            FENCE_ASYNC_SHARED();
            uint64_t dah = make_desc_sw128(sb + boff + OFF_AH);
            uint64_t dal = make_desc_sw128(sb + boff + OFF_AL);
            uint64_t dbh = make_desc_sw128(sb + boff + OFF_BH);
            uint64_t dbl = make_desc_sw128(sb + boff + OFF_BL);
#pragma unroll
            for (int ks = 0; ks < 4; ks++) {
                mma_f16_ss(tmem, dah + ks * 2, dbh + ks * 2, GIDESC, first ? 0u : 1u);
                first = 0;
                mma_f16_ss(tmem, dah + ks * 2, dbl + ks * 2, GIDESC, 1u);
                mma_f16_ss(tmem, dal + ks * 2, dbh + ks * 2, GIDESC, 1u);
            }
            TC_COMMIT(buf == 0 ? mb0 : mb1);
        }
    }

    mbar_wait(mb1, (uint32_t)ph1);
    TC_FENCE_AFTER();

    int sub  = wid & 3;
    int colb = (wid >> 2) * 64;
    int row  = m0 + sub * 32 + (int)lid;
    size_t rowoff = (size_t)row * DM + n0 + colb;

    uint32_t d0[32], d1[32];
    tc_ld_x32(d0, tmem + colb);
    tc_ld_x32(d1, tmem + colb + 32);
    TC_WAIT_LD();

    if (mode == 0) {
        float* Cr = C + rowoff;
#pragma unroll
        for (int j = 0; j < 8; j++)
            *(float4*)(Cr + j * 4) = make_float4(
                __uint_as_float(d0[4*j]),   __uint_as_float(d0[4*j+1]),
                __uint_as_float(d0[4*j+2]), __uint_as_float(d0[4*j+3]));
#pragma unroll
        for (int j = 0; j < 8; j++)
            *(float4*)(Cr + 32 + j * 4) = make_float4(
                __uint_as_float(d1[4*j]),   __uint_as_float(d1[4*j+1]),
                __uint_as_float(d1[4*j+2]), __uint_as_float(d1[4*j+3]));
    } else {
        uint32_t hw[32], lw[32];
#pragma unroll
        for (int m = 0; m < 16; m++) {
            float v0 = __uint_as_float(d0[2*m])   * scale;
            float v1 = __uint_as_float(d0[2*m+1]) * scale;
            __nv_bfloat162 h2 = __floats2bfloat162_rn(v0, v1);
            __nv_bfloat162 l2 = __floats2bfloat162_rn(v0 - __bfloat162float(h2.x),
                                                      v1 - __bfloat162float(h2.y));
            hw[m] = *(uint32_t*)&h2; lw[m] = *(uint32_t*)&l2;
        }
#pragma unroll
        for (int m = 0; m < 16; m++) {
            float v0 = __uint_as_float(d1[2*m])   * scale;
            float v1 = __uint_as_float(d1[2*m+1]) * scale;
            __nv_bfloat162 h2 = __floats2bfloat162_rn(v0, v1);
            __nv_bfloat162 l2 = __floats2bfloat162_rn(v0 - __bfloat162float(h2.x),
                                                      v1 - __bfloat162float(h2.y));
            hw[16 + m] = *(uint32_t*)&h2; lw[16 + m] = *(uint32_t*)&l2;
        }
#pragma unroll
        for (int u = 0; u < 8; u++) {
            *(uint4*)(Ch + rowoff + u * 8) =
                make_uint4(hw[4*u], hw[4*u+1], hw[4*u+2], hw[4*u+3]);
            *(uint4*)(Cl + rowoff + u * 8) =
                make_uint4(lw[4*u], lw[4*u+1], lw[4*u+2], lw[4*u+3]);
        }
    }
    TC_FENCE_BEFORE();
    __syncthreads();
    if (wid == 0) TC_DEALLOC(tmem, 128);

#else   // ---------------- SIMT fallback ----------------
    float* As = (float*)dsm_raw;
    float* Ws = As + 2 * 8 * 132;
    int tx = tid & 15, ty = (int)(tid >> 4);
    int r = tid & 127;
    bool isA = tid < 128;
    const __nv_bfloat16* Ph = isA ? Ah + (size_t)(m0 + r) * DM
                                  : Bh + (size_t)(n0 + r) * DM;
    const __nv_bfloat16* Pl = isA ? Al + (size_t)(m0 + r) * DM
                                  : Bl + (size_t)(n0 + r) * DM;
    int stride = isA ? 132 : 128;

    float acc[8][8];
#pragma unroll
    for (int i = 0; i < 8; i++)
#pragma unroll
        for (int j = 0; j < 8; j++) acc[i][j] = 0.f;

    auto stage = [&](int buf, int k0) {
        uint4 vh = *(const uint4*)(Ph + k0);
        uint4 vl = *(const uint4*)(Pl + k0);
        const __nv_bfloat16* bh = (const __nv_bfloat16*)&vh;
        const __nv_bfloat16* bl = (const __nv_bfloat16*)&vl;
        float* dst = (isA ? As + buf * 8 * 132 : Ws + buf * 8 * 128) + r;
#pragma unroll
        for (int k = 0; k < 8; k++)
            dst[k * stride] = __bfloat162float(bh[k]) + __bfloat162float(bl[k]);
    };
    stage(0, 0);
    __syncthreads();
    int buf = 0;
#pragma unroll 1
    for (int k0 = 0; k0 < 512; k0 += 8) {
        if (k0 + 8 < 512) stage(buf ^ 1, k0 + 8);
#pragma unroll
        for (int kk = 0; kk < 8; kk++) {
            float av[8], bv[8];
            const float* ar = As + buf * 8 * 132 + kk * 132;
            const float* wr = Ws + buf * 8 * 128 + kk * 128;
            *(float4*)(av)     = *(const float4*)(ar + ty * 4);
            *(float4*)(av + 4) = *(const float4*)(ar + 64 + ty * 4);
            *(float4*)(bv)     = *(const float4*)(wr + tx * 4);
            *(float4*)(bv + 4) = *(const float4*)(wr + 64 + tx * 4);
#pragma unroll
            for (int i = 0; i < 8; i++)
#pragma unroll
                for (int j = 0; j < 8; j++) acc[i][j] += av[i] * bv[j];
        }
        __syncthreads();
        buf ^= 1;
    }
#pragma unroll
    for (int i = 0; i < 8; i++) {
        int row = m0 + ((i < 4) ? (ty * 4 + i) : (64 + ty * 4 + i - 4));
#pragma unroll
        for (int j = 0; j < 8; j++) {
            int col = n0 + ((j < 4) ? (tx * 4 + j) : (64 + tx * 4 + j - 4));
            float v = acc[i][j];
            if (mode == 0) C[(size_t)row * DM + col] = v;
            else {
                v *= scale;
                __nv_bfloat16 h = __float2bfloat16(v);
                Ch[(size_t)row * DM + col] = h;
                Cl[(size_t)row * DM + col] =
                    __float2bfloat16(v - __bfloat162float(h));
            }
        }
    }
#endif
}

// ================ attention ================
#define AIDESC ((1u << 4) | (1u << 7) | (1u << 10) | ((64u / 8) << 17) | ((128u / 16) << 24))
#define ATTN_DSMEM (132096 + 1024)

#if HAS_TC
__global__ void __launch_bounds__(256, 1)
attn_kernel(const __nv_bfloat16* __restrict__ Qh, const __nv_bfloat16* __restrict__ Ql,
            const __nv_bfloat16* __restrict__ Kh, const __nv_bfloat16* __restrict__ Kl,
            const __nv_bfloat16* __restrict__ Vth, const __nv_bfloat16* __restrict__ Vtl,
            const float* __restrict__ Vf,
            __nv_bfloat16* __restrict__ Oh, __nv_bfloat16* __restrict__ Ol) {
    extern __shared__ char dsm_raw[];
    __shared__ __align__(16) uint64_t s_mbar[2];
    __shared__ uint32_t s_tm[1];
    uint32_t tid = threadIdx.x, wid = tid >> 5, lane = tid & 31;
    int qt = (int)(gridDim.x - 1) - (int)blockIdx.x;     // heavy tiles first
    int bh = blockIdx.y, bb = bh >> 3, hd = bh & 7;

    uint32_t raw = smem_u32(dsm_raw);
    uint32_t sb  = (raw + 1023) & ~1023u;
    char* dsm = dsm_raw + (sb - raw);

    const uint32_t OFF_QH = 0,     OFF_QL = 16384, OFF_KH = 32768, OFF_KL = 49152,
                   OFF_VH = 65536, OFF_VL = 81920, OFF_PH = 98304, OFF_PL = 114688,
                   OFF_L  = 131072;

    uint32_t mbS  = smem_u32(&s_mbar[0]);
    uint32_t mbPV = smem_u32(&s_mbar[1]);
    if (wid == 0) TC_ALLOC(smem_u32(s_tm), 128);
    if (tid == 0) { MBAR_INIT(mbS, 1); MBAR_INIT(mbPV, 1); }
    __syncthreads();
    uint32_t tmem = s_tm[0];

    size_t rowbase = (size_t)bb * SEQ;

    // load Q tile (pre-scaled splits)
    {
        const __nv_bfloat16* qhp = Qh + (rowbase + (size_t)qt * 128) * DM + hd * 64;
        const __nv_bfloat16* qlp = Ql + (rowbase + (size_t)qt * 128) * DM + hd * 64;
#pragma unroll
        for (int i = 0; i < 4; i++) {
            int idx = i * 256 + (int)tid;
            int r = idx >> 3, g = idx & 7;
            uint32_t o = (uint32_t)(r * 128 + g * 16), so = o ^ ((o >> 3) & 0x70);
            *(uint4*)(dsm + OFF_QH + so) = *(const uint4*)(qhp + (size_t)r * DM + g * 8);
            *(uint4*)(dsm + OFF_QL + so) = *(const uint4*)(qlp + (size_t)r * DM + g * 8);
        }
    }

    int sub = wid & 3, half = (int)(wid >> 2);
    int rl = sub * 32 + (int)lane;
    int grow = qt * 128 + rl;
    float lsum = 0.f;
    uint32_t phS = 0, phPV = 0;
    int ktmax = 2 * qt + 1;

#pragma unroll 1
    for (int kt = 0; kt <= ktmax; kt++) {
        int buf = kt & 1;
        uint32_t kb  = OFF_KH + (uint32_t)buf * 8192u;
        uint32_t klb = OFF_KL + (uint32_t)buf * 8192u;
        uint32_t vb  = OFF_VH + (uint32_t)buf * 8192u;
        uint32_t vlb = OFF_VL + (uint32_t)buf * 8192u;

        const __nv_bfloat16* khp = Kh + (rowbase + (size_t)kt * 64) * DM + hd * 64;
        const __nv_bfloat16* klp = Kl + (rowbase + (size_t)kt * 64) * DM + hd * 64;
        const __nv_bfloat16* vhp = Vth + ((size_t)bh * 64) * SEQ + (size_t)kt * 64;
        const __nv_bfloat16* vlp = Vtl + ((size_t)bh * 64) * SEQ + (size_t)kt * 64;
#pragma unroll
        for (int i = 0; i < 2; i++) {
            int idx = i * 256 + (int)tid;
            int r = idx >> 3, g = idx & 7;
            uint32_t o = (uint32_t)(r * 128 + g * 16), so = o ^ ((o >> 3) & 0x70);
            *(uint4*)(dsm + kb  + so) = *(const uint4*)(khp + (size_t)r * DM + g * 8);
            *(uint4*)(dsm + klb + so) = *(const uint4*)(klp + (size_t)r * DM + g * 8);
            *(uint4*)(dsm + vb  + so) = *(const uint4*)(vhp + (size_t)r * SEQ + g * 8);
            *(uint4*)(dsm + vlb + so) = *(const uint4*)(vlp + (size_t)r * SEQ + g * 8);
        }
        __syncthreads();

        if (wid == 0 && elect1()) {
            FENCE_ASYNC_SHARED();
            uint64_t dqh = make_desc_sw128(sb + OFF_QH);
            uint64_t dql = make_desc_sw128(sb + OFF_QL);
            uint64_t dkh = make_desc_sw128(sb + kb);
            uint64_t dkl = make_desc_sw128(sb + klb);
#pragma unroll
            for (int ks = 0; ks < 4; ks++)
                mma_f16_ss(tmem, dqh + ks * 2, dkh + ks * 2, AIDESC, ks ? 1u : 0u);
#pragma unroll
            for (int ks = 0; ks < 4; ks++)
                mma_f16_ss(tmem, dqh + ks * 2, dkl + ks * 2, AIDESC, 1u);
#pragma unroll
            for (int ks = 0; ks < 4; ks++)
                mma_f16_ss(tmem, dql + ks * 2, dkh + ks * 2, AIDESC, 1u);
            TC_COMMIT(mbS);
        }
        mbar_wait(mbS, phS); phS ^= 1;
        TC_FENCE_AFTER();

        uint32_t sreg[32];
        tc_ld_x32(sreg, tmem + half * 32);
        TC_WAIT_LD();

        int jmax = grow - (kt * 64 + half * 32);
        if (kt) { mbar_wait(mbPV, phPV); phPV ^= 1; }

        uint32_t pbase = (uint32_t)(rl * 128 + half * 64);
#pragma unroll
        for (int gj = 0; gj < 4; gj++) {
            uint32_t hw[4], lw[4];
#pragma unroll
            for (int m = 0; m < 4; m++) {
                int j0 = gj * 8 + m * 2;
                float p0 = (j0     <= jmax) ? fast_exp2(__uint_as_float(sreg[j0]))     : 0.f;
                float p1 = (j0 + 1 <= jmax) ? fast_exp2(__uint_as_float(sreg[j0 + 1])) : 0.f;
                lsum += p0 + p1;
                __nv_bfloat162 h2 = __floats2bfloat162_rn(p0, p1);
                __nv_bfloat162 l2 = __floats2bfloat162_rn(p0 - __bfloat162float(h2.x),
                                                          p1 - __bfloat162float(h2.y));
                hw[m] = *(uint32_t*)&h2;
                lw[m] = *(uint32_t*)&l2;
            }
            uint32_t o = pbase + gj * 16, so = o ^ ((o >> 3) & 0x70);
            *(uint4*)(dsm + OFF_PH + so) = make_uint4(hw[0], hw[1], hw[2], hw[3]);
            *(uint4*)(dsm + OFF_PL + so) = make_uint4(lw[0], lw[1], lw[2], lw[3]);
        }
        __syncthreads();

        if (wid == 0 && elect1()) {
            FENCE_ASYNC_SHARED();
            uint64_t dph = make_desc_sw128(sb + OFF_PH);
            uint64_t dpl = make_desc_sw128(sb + OFF_PL);
            uint64_t dvh = make_desc_sw128(sb + vb);
            uint64_t dvl = make_desc_sw128(sb + vlb);
#pragma unroll
            for (int ks = 0; ks < 4; ks++)
                mma_f16_ss(tmem + 64, dph + ks * 2, dvh + ks * 2, AIDESC,
                           (kt == 0 && ks == 0) ? 0u : 1u);
#pragma unroll
            for (int ks = 0; ks < 4; ks++)
                mma_f16_ss(tmem + 64, dph + ks * 2, dvl + ks * 2, AIDESC, 1u);
#pragma unroll
            for (int ks = 0; ks < 4; ks++)
                mma_f16_ss(tmem + 64, dpl + ks * 2, dvh + ks * 2, AIDESC, 1u);
            TC_COMMIT(mbPV);
        }
    }

    mbar_wait(mbPV, phPV);
    TC_FENCE_AFTER();

    float* sl = (float*)(dsm + OFF_L);
    sl[rl * 2 + half] = lsum;
    __syncthreads();
    float inv = 1.f / (sl[rl * 2] + sl[rl * 2 + 1]);

    uint32_t oreg[32];
    tc_ld_x32(oreg, tmem + 64 + half * 32);
    TC_WAIT_LD();
    TC_FENCE_BEFORE();

    size_t obase = (rowbase + (size_t)grow) * DM + hd * 64 + half * 32;
    uint32_t hw[16], lw[16];
#pragma unroll
    for (int m = 0; m < 16; m++) {
        float v0 = __uint_as_float(oreg[2*m])   * inv;
        float v1 = __uint_as_float(oreg[2*m+1]) * inv;
        __nv_bfloat162 h2 = __floats2bfloat162_rn(v0, v1);
        __nv_bfloat162 l2 = __floats2bfloat162_rn(v0 - __bfloat162float(h2.x),
                                                  v1 - __bfloat162float(h2.y));
        hw[m] = *(uint32_t*)&h2; lw[m] = *(uint32_t*)&l2;
    }
#pragma unroll
    for (int u = 0; u < 4; u++) {
        *(uint4*)(Oh + obase + u * 8) = make_uint4(hw[4*u], hw[4*u+1], hw[4*u+2], hw[4*u+3]);
        *(uint4*)(Ol + obase + u * 8) = make_uint4(lw[4*u], lw[4*u+1], lw[4*u+2], lw[4*u+3]);
    }
    __syncthreads();
    if (wid == 0) TC_DEALLOC(tmem, 128);
}

#else  // ---------------- SIMT fallback attention ----------------
#define QT 128
#define KTILE 64
#define SQS 68
#define SKS 68
#define SPS 68

__global__ void __launch_bounds__(256, 1)
attn_kernel(const __nv_bfloat16* __restrict__ Qh, const __nv_bfloat16* __restrict__ Ql,
            const __nv_bfloat16* __restrict__ Kh, const __nv_bfloat16* __restrict__ Kl,
            const __nv_bfloat16* __restrict__ Vth, const __nv_bfloat16* __restrict__ Vtl,
            const float* __restrict__ Vf,
            __nv_bfloat16* __restrict__ Oh, __nv_bfloat16* __restrict__ Ol) {
    extern __shared__ float sm[];
    float* sQ = sm;
    float* sK = sQ + QT * SQS;
    float* sV = sK + KTILE * SKS;
    float* sP = sV + KTILE * 64;

    int qt = (int)(gridDim.x - 1) - (int)blockIdx.x;
    int bh = blockIdx.y;
    int bb = bh >> 3, hd = bh & 7;
    int tid = threadIdx.x;
    int tx = tid & 15, ty = tid >> 4;
    size_t base = ((size_t)bb * SEQ) * DM + (size_t)hd * DK;

    for (int idx = tid; idx < QT * 64; idx += 256) {
        int r = idx >> 6, c = idx & 63;
        size_t o = base + (size_t)(qt * QT + r) * DM + c;
        sQ[r * SQS + c] = __bfloat162float(Qh[o]) + __bfloat162float(Ql[o]);
    }

    float Oacc[8][4];
    float m_i[8], l_i[8];
#pragma unroll
    for (int i = 0; i < 8; i++) {
        m_i[i] = -1e30f; l_i[i] = 0.f;
#pragma unroll
        for (int j = 0; j < 4; j++) Oacc[i][j] = 0.f;
    }

    int ktmax = 2 * qt + 1;
    for (int kt = 0; kt <= ktmax; kt++) {
        for (int idx = tid; idx < KTILE * 64; idx += 256) {
            int r = idx >> 6, c = idx & 63;
            size_t ga = base + (size_t)(kt * KTILE + r) * DM + c;
            sK[r * SKS + c] = __bfloat162float(Kh[ga]) + __bfloat162float(Kl[ga]);
            sV[r * 64 + c]  = Vf[ga];
        }
        __syncthreads();

        float s[8][4];
#pragma unroll
        for (int i = 0; i < 8; i++)
#pragma unroll
            for (int j = 0; j < 4; j++) s[i][j] = 0.f;
#pragma unroll
        for (int d4 = 0; d4 < 16; d4++) {
            float4 kv[4];
#pragma unroll
            for (int j = 0; j < 4; j++)
                kv[j] = *(const float4*)&sK[(tx + 16 * j) * SKS + d4 * 4];
#pragma unroll
            for (int i = 0; i < 8; i++) {
                float4 qv = *(const float4*)&sQ[(ty + 16 * i) * SQS + d4 * 4];
#pragma unroll
                for (int j = 0; j < 4; j++)
                    s[i][j] += qv.x * kv[j].x + qv.y * kv[j].y +
                               qv.z * kv[j].z + qv.w * kv[j].w;
            }
        }
        if (kt >= 2 * qt) {
#pragma unroll
            for (int i = 0; i < 8; i++) {
                int grow = qt * QT + ty + 16 * i;
#pragma unroll
                for (int j = 0; j < 4; j++)
                    if (kt * KTILE + tx + 16 * j > grow) s[i][j] = -1e30f;
            }
        }
#pragma unroll
        for (int i = 0; i < 8; i++) {
            float mt = fmaxf(fmaxf(s[i][0], s[i][1]), fmaxf(s[i][2], s[i][3]));
#pragma unroll
            for (int off = 8; off; off >>= 1)
                mt = fmaxf(mt, __shfl_xor_sync(0xffffffffu, mt, off));
            float mn = fmaxf(m_i[i], mt);
            float corr = exp2f(m_i[i] - mn);
            m_i[i] = mn;
            float rs = 0.f;
#pragma unroll
            for (int j = 0; j < 4; j++) {
                float p = exp2f(s[i][j] - mn);
                s[i][j] = p; rs += p;
            }
#pragma unroll
            for (int off = 8; off; off >>= 1)
                rs += __shfl_xor_sync(0xffffffffu, rs, off);
            l_i[i] = l_i[i] * corr + rs;
#pragma unroll
            for (int j = 0; j < 4; j++) Oacc[i][j] *= corr;
#pragma unroll
            for (int j = 0; j < 4; j++)
                sP[(ty + 16 * i) * SPS + tx + 16 * j] = s[i][j];
        }
        __syncthreads();
#pragma unroll 4
        for (int k = 0; k < KTILE; k += 4) {
            float4 vv0 = *(const float4*)&sV[(k + 0) * 64 + tx * 4];
            float4 vv1 = *(const float4*)&sV[(k + 1) * 64 + tx * 4];
            float4 vv2 = *(const float4*)&sV[(k + 2) * 64 + tx * 4];
            float4 vv3 = *(const float4*)&sV[(k + 3) * 64 + tx * 4];
#pragma unroll
            for (int i = 0; i < 8; i++) {
                float4 pv = *(const float4*)&sP[(ty + 16 * i) * SPS + k];
                Oacc[i][0] += pv.x * vv0.x + pv.y * vv1.x + pv.z * vv2.x + pv.w * vv3.x;
                Oacc[i][1] += pv.x * vv0.y + pv.y * vv1.y + pv.z * vv2.y + pv.w * vv3.y;
                Oacc[i][2] += pv.x * vv0.z + pv.y * vv1.z + pv.z * vv2.z + pv.w * vv3.z;
                Oacc[i][3] += pv.x * vv0.w + pv.y * vv1.w + pv.z * vv2.w + pv.w * vv3.w;
            }
        }
        __syncthreads();
    }
#pragma unroll
    for (int i = 0; i < 8; i++) {
        float inv = 1.f / l_i[i];
        size_t rowa = base + (size_t)(qt * QT + ty + 16 * i) * DM + tx * 4;
#pragma unroll
        for (int j = 0; j < 4; j++) {
            float v = Oacc[i][j] * inv;
            __nv_bfloat16 h = __float2bfloat16(v);
            Oh[rowa + j] = h;
            Ol[rowa + j] = __float2bfloat16(v - __bfloat162float(h));
        }
    }
}
#endif

// ---------------- launch ----------------
extern "C" void kernel_launch(void* const* d_in, const int* in_sizes, int n_in,
                              void* d_out, int out_size) {
    const float* x     = (const float*)d_in[0];
    const float* ln1_g = (const float*)d_in[1];
    const float* ln1_b = (const float*)d_in[2];
    const float* wq    = (const float*)d_in[3];
    const float* wk    = (const float*)d_in[4];
    const float* wv    = (const float*)d_in[5];
    const float* wfc   = (const float*)d_in[6];
    const float* ln2_g = (const float*)d_in[7];
    const float* ln2_b = (const float*)d_in[8];
    float* out = (float*)d_out;

    float *ppe, *ph, *pv;
    __nv_bfloat16 *pwh, *pwl, *pah, *pal, *pqh, *pql, *pkh, *pkl, *poh, *pol, *pvth, *pvtl;
    cudaGetSymbolAddress((void**)&ppe,  g_pe);
    cudaGetSymbolAddress((void**)&ph,   g_h);
    cudaGetSymbolAddress((void**)&pv,   g_v);
    cudaGetSymbolAddress((void**)&pwh,  g_wth);
    cudaGetSymbolAddress((void**)&pwl,  g_wtl);
    cudaGetSymbolAddress((void**)&pah,  g_ah);
    cudaGetSymbolAddress((void**)&pal,  g_al);
    cudaGetSymbolAddress((void**)&pqh,  g_qh);
    cudaGetSymbolAddress((void**)&pql,  g_ql);
    cudaGetSymbolAddress((void**)&pkh,  g_kh);
    cudaGetSymbolAddress((void**)&pkl,  g_kl);
    cudaGetSymbolAddress((void**)&poh,  g_oh);
    cudaGetSymbolAddress((void**)&pol,  g_ol);
    cudaGetSymbolAddress((void**)&pvth, g_vth);
    cudaGetSymbolAddress((void**)&pvtl, g_vtl);

    cudaFuncSetAttribute(attn_kernel,
                         cudaFuncAttributeMaxDynamicSharedMemorySize, ATTN_DSMEM);
    cudaFuncSetAttribute(gemm_tc_kernel,
                         cudaFuncAttributeMaxDynamicSharedMemorySize, GEMM_DSMEM);

    pe_kernel<<<SEQ, 256>>>(ppe);

    dim3 wt(32, 8);
    dim3 wgrid(16, 16);
    const float* ws[4] = {wq, wk, wv, wfc};
    for (int i = 0; i < 4; i++)
        wsplit_kernel<<<wgrid, wt>>>(ws[i], pwh + (size_t)i * DM * DM,
                                            pwl + (size_t)i * DM * DM);

    ln1_pos_kernel<<<ROWS, 256>>>(x, ln1_g, ln1_b, ppe, ph, pah, pal);

    const float qscale = 0.125f * 1.4426950408889634f;
    dim3 gg(ROWS / 128, DM / 128);
    gemm_tc_kernel<<<gg, 256, GEMM_DSMEM>>>(pah, pal,
        pwh + 0 * (size_t)DM * DM, pwl + 0 * (size_t)DM * DM,
        nullptr, pqh, pql, qscale, 1);
    gemm_tc_kernel<<<gg, 256, GEMM_DSMEM>>>(pah, pal,
        pwh + 1 * (size_t)DM * DM, pwl + 1 * (size_t)DM * DM,
        nullptr, pkh, pkl, 1.0f, 1);
    gemm_tc_kernel<<<gg, 256, GEMM_DSMEM>>>(pah, pal,
        pwh + 2 * (size_t)DM * DM, pwl + 2 * (size_t)DM * DM,
        pv, nullptr, nullptr, 1.0f, 0);

    dim3 vg(SEQ / 64, BATCH * NH);
    vtrans_kernel<<<vg, 256>>>(pv, pvth, pvtl);

    dim3 ga(SEQ / 128, BATCH * NH);
    attn_kernel<<<ga, 256, ATTN_DSMEM>>>(pqh, pql, pkh, pkl, pvth, pvtl, pv, poh, pol);

    gemm_tc_kernel<<<gg, 256, GEMM_DSMEM>>>(poh, pol,
        pwh + 3 * (size_t)DM * DM, pwl + 3 * (size_t)DM * DM,
        pv, nullptr, nullptr, 1.0f, 0);

    ln2_kernel<<<ROWS, 256>>>(pv, ph, x, ln2_g, ln2_b, out);
}

// round 6
// speedup vs baseline: 3.7952x; 1.2897x over previous
#include <cuda_runtime.h>
#include <cuda_bf16.h>
#include <cuda_fp16.h>
#include <math.h>
#include <stdint.h>

#define BATCH 4
#define SEQ   2048
#define DM    512
#define NH    8
#define DK    64
#define ROWS  (BATCH * SEQ)   // 8192

#if defined(__CUDA_ARCH_FEAT_SM103_ALL) || defined(__CUDA_ARCH_FEAT_SM100_ALL) || \
    defined(__CUDA_ARCH_SPECIFIC__) || defined(__CUDA_ARCH_FAMILY_SPECIFIC__)
#define HAS_TC 1
#else
#define HAS_TC 0
#endif

// ---------------- scratch ----------------
__device__ float g_pe[SEQ * DM];
__device__ float g_h [ROWS * DM];            // residual1 (fp32)
__device__ float g_fc[ROWS * DM];            // fc output fp32
__device__ __nv_bfloat16 g_ah[ROWS * DM];    // h split hi
__device__ __nv_bfloat16 g_al[ROWS * DM];
__device__ __nv_bfloat16 g_qh[ROWS * DM];    // q (pre-scaled) splits
__device__ __nv_bfloat16 g_ql[ROWS * DM];
__device__ __nv_bfloat16 g_kh[ROWS * DM];
__device__ __nv_bfloat16 g_kl[ROWS * DM];
__device__ __nv_bfloat16 g_oh[ROWS * DM];    // attn out splits
__device__ __nv_bfloat16 g_ol[ROWS * DM];
__device__ __half        g_vt[BATCH * NH * DK * SEQ];   // V^T fp16 [bh][dim][key]
__device__ __nv_bfloat16 g_wth[4][DM * DM];  // W^T hi, [n][k]
__device__ __nv_bfloat16 g_wtl[4][DM * DM];

// ================= helpers =================
__device__ __forceinline__ uint32_t smem_u32(const void* p) {
    uint32_t a;
    asm("{ .reg .u64 t; cvta.to.shared.u64 t, %1; cvt.u32.u64 %0, t; }"
        : "=r"(a) : "l"(p));
    return a;
}

__device__ __forceinline__ float fast_exp2(float x) {
    x = fminf(fmaxf(x, -120.f), 120.f);
    int   ii = __float2int_rn(x);
    float f  = x - (float)ii;
    float p  = 1.5403530394e-4f;
    p = fmaf(p, f, 1.3333558146e-3f);
    p = fmaf(p, f, 9.6181291076e-3f);
    p = fmaf(p, f, 5.5504108665e-2f);
    p = fmaf(p, f, 2.4022650696e-1f);
    p = fmaf(p, f, 6.9314718056e-1f);
    p = fmaf(p, f, 1.0f);
    return p * __int_as_float((ii + 127) << 23);
}

#if HAS_TC
__device__ __forceinline__ uint32_t elect1() {
    uint32_t p;
    asm volatile("{\n\t.reg .pred p;\n\telect.sync _|p, 0xFFFFFFFF;\n\t"
                 "selp.b32 %0, 1, 0, p;\n\t}" : "=r"(p));
    return p;
}
#define TC_ALLOC(smemaddr, ncols) \
    asm volatile("tcgen05.alloc.cta_group::1.sync.aligned.shared::cta.b32 [%0], %1;" \
                 :: "r"(smemaddr), "r"(ncols) : "memory")
#define TC_RELINQ() \
    asm volatile("tcgen05.relinquish_alloc_permit.cta_group::1.sync.aligned;")
#define TC_DEALLOC(tmem, ncols) \
    asm volatile("tcgen05.dealloc.cta_group::1.sync.aligned.b32 %0, %1;" \
                 :: "r"(tmem), "r"(ncols))
#define TC_COMMIT(mbar) \
    asm volatile("tcgen05.commit.cta_group::1.mbarrier::arrive::one.shared::cluster.b64 [%0];" \
                 :: "r"(mbar) : "memory")
#define TC_FENCE_AFTER()  asm volatile("tcgen05.fence::after_thread_sync;" ::: "memory")
#define TC_FENCE_BEFORE() asm volatile("tcgen05.fence::before_thread_sync;" ::: "memory")
#define TC_WAIT_LD()      asm volatile("tcgen05.wait::ld.sync.aligned;" ::: "memory")
#define FENCE_ASYNC_SHARED() asm volatile("fence.proxy.async.shared::cta;" ::: "memory")
#define MBAR_INIT(mbar, cnt) \
    asm volatile("mbarrier.init.shared.b64 [%0], %1;" :: "r"(mbar), "r"(cnt) : "memory")

__device__ __forceinline__ void mbar_wait(uint32_t mbar, uint32_t parity) {
    asm volatile(
        "{\n\t.reg .pred P;\n\t"
        "WL_%=:\n\t"
        "mbarrier.try_wait.parity.acquire.cta.shared::cta.b64 P, [%0], %1, 0x989680;\n\t"
        "@P bra.uni WD_%=;\n\t"
        "bra.uni WL_%=;\n\t"
        "WD_%=:\n\t}"
        :: "r"(mbar), "r"(parity) : "memory");
}

__device__ __forceinline__ void tc_ld_x32(uint32_t* r, uint32_t tmem_addr) {
    asm volatile(
        "tcgen05.ld.sync.aligned.32x32b.x32.b32 "
        "{%0, %1, %2, %3, %4, %5, %6, %7, %8, %9, %10, %11, %12, %13, %14, %15, "
        " %16, %17, %18, %19, %20, %21, %22, %23, %24, %25, %26, %27, %28, %29, %30, %31}, [%32];"
        : "=r"(r[0]),  "=r"(r[1]),  "=r"(r[2]),  "=r"(r[3]),
          "=r"(r[4]),  "=r"(r[5]),  "=r"(r[6]),  "=r"(r[7]),
          "=r"(r[8]),  "=r"(r[9]),  "=r"(r[10]), "=r"(r[11]),
          "=r"(r[12]), "=r"(r[13]), "=r"(r[14]), "=r"(r[15]),
          "=r"(r[16]), "=r"(r[17]), "=r"(r[18]), "=r"(r[19]),
          "=r"(r[20]), "=r"(r[21]), "=r"(r[22]), "=r"(r[23]),
          "=r"(r[24]), "=r"(r[25]), "=r"(r[26]), "=r"(r[27]),
          "=r"(r[28]), "=r"(r[29]), "=r"(r[30]), "=r"(r[31])
        : "r"(tmem_addr));
}

__device__ __forceinline__ void mma_f16_ss(uint32_t d, uint64_t a, uint64_t b,
                                           uint32_t idesc, uint32_t en) {
    asm volatile(
        "{\n\t.reg .pred p;\n\tsetp.ne.u32 p, %4, 0;\n\t"
        "tcgen05.mma.cta_group::1.kind::f16 [%0], %1, %2, %3, {%5, %5, %5, %5}, p;\n\t}"
        :: "r"(d), "l"(a), "l"(b), "r"(idesc), "r"(en), "r"(0u) : "memory");
}

static __device__ __forceinline__ uint64_t make_desc_sw128(uint32_t base) {
    const uint64_t BASE =
        (uint64_t(2) << 61) | (uint64_t(1) << 46) | (uint64_t(64) << 32) | (uint64_t(1) << 16);
    return BASE | ((uint64_t)(base >> 4) & 0x3FFF);
}
#endif  // HAS_TC

// ---------------- positional encoding (fp64) ----------------
__global__ void pe_kernel(float* __restrict__ pe) {
    int t   = blockIdx.x;
    int tid = threadIdx.x;
    const double c = -(9.210340371976184 / 512.0);
#pragma unroll
    for (int u = 0; u < 2; u++) {
        int col = tid + u * 256;
        int i2  = col & ~1;
        double arg = (double)t * exp((double)i2 * c);
        pe[t * DM + col] = (col & 1) ? (float)cos(arg) : (float)sin(arg);
    }
}

// ---------------- W transpose + bf16 split (3 weights, z-indexed) ------------
__global__ void wsplit3_kernel(const float* __restrict__ W0,
                               const float* __restrict__ W1,
                               const float* __restrict__ W2,
                               __nv_bfloat16* __restrict__ Th,
                               __nv_bfloat16* __restrict__ Tl) {
    __shared__ float t[32][33];
    int z = blockIdx.z;
    const float* W = (z == 0) ? W0 : (z == 1) ? W1 : W2;
    __nv_bfloat16* th = Th + (size_t)z * DM * DM;
    __nv_bfloat16* tl = Tl + (size_t)z * DM * DM;
    int n0 = blockIdx.x * 32, k0 = blockIdx.y * 32;
    int tx = threadIdx.x, ty = threadIdx.y;
#pragma unroll
    for (int i = 0; i < 32; i += 8)
        t[ty + i][tx] = W[(size_t)(k0 + ty + i) * DM + n0 + tx];
    __syncthreads();
#pragma unroll
    for (int i = 0; i < 32; i += 8) {
        float v = t[tx][ty + i];
        __nv_bfloat16 h = __float2bfloat16(v);
        __nv_bfloat16 l = __float2bfloat16(v - __bfloat162float(h));
        size_t o = (size_t)(n0 + ty + i) * DM + k0 + tx;
        th[o] = h; tl[o] = l;
    }
}

__global__ void wsplit_kernel(const float* __restrict__ W,
                              __nv_bfloat16* __restrict__ Th,
                              __nv_bfloat16* __restrict__ Tl) {
    __shared__ float t[32][33];
    int n0 = blockIdx.x * 32, k0 = blockIdx.y * 32;
    int tx = threadIdx.x, ty = threadIdx.y;
#pragma unroll
    for (int i = 0; i < 32; i += 8)
        t[ty + i][tx] = W[(size_t)(k0 + ty + i) * DM + n0 + tx];
    __syncthreads();
#pragma unroll
    for (int i = 0; i < 32; i += 8) {
        float v = t[tx][ty + i];
        __nv_bfloat16 h = __float2bfloat16(v);
        __nv_bfloat16 l = __float2bfloat16(v - __bfloat162float(h));
        size_t o = (size_t)(n0 + ty + i) * DM + k0 + tx;
        Th[o] = h; Tl[o] = l;
    }
}

// ---------------- LN1 + pe (+ bf16 split of h) ----------------
__global__ void ln1_pos_kernel(const float* __restrict__ x,
                               const float* __restrict__ gam,
                               const float* __restrict__ bet,
                               const float* __restrict__ pe,
                               float* __restrict__ h,
                               __nv_bfloat16* __restrict__ hh,
                               __nv_bfloat16* __restrict__ hl) {
    __shared__ float redS[8], redS2[8];
    int row = blockIdx.x;
    int t   = row & (SEQ - 1);
    const float* xr = x  + (size_t)row * DM;
    const float* pr = pe + (size_t)t   * DM;
    int tid = threadIdx.x;

    float a = xr[tid], b = xr[tid + 256];
    float s  = a + b;
    float s2 = a * a + b * b;
#pragma unroll
    for (int off = 16; off; off >>= 1) {
        s  += __shfl_xor_sync(0xffffffffu, s,  off);
        s2 += __shfl_xor_sync(0xffffffffu, s2, off);
    }
    if ((tid & 31) == 0) { redS[tid >> 5] = s; redS2[tid >> 5] = s2; }
    __syncthreads();
    if (tid == 0) {
        float S = 0.f, S2 = 0.f;
#pragma unroll
        for (int w = 0; w < 8; w++) { S += redS[w]; S2 += redS2[w]; }
        redS[0] = S; redS2[0] = S2;
    }
    __syncthreads();
    float mu   = redS[0] * (1.f / 512.f);
    float var  = redS2[0] * (1.f / 512.f) - mu * mu;
    float rstd = rsqrtf(var + 1e-5f);
#pragma unroll
    for (int u = 0; u < 2; u++) {
        int col = tid + u * 256;
        float xv = u ? b : a;
        float hv = (xv - mu) * rstd * gam[col] + bet[col] + pr[col];
        size_t o = (size_t)row * DM + col;
        h[o] = hv;
        __nv_bfloat16 hi = __float2bfloat16(hv);
        hh[o] = hi;
        hl[o] = __float2bfloat16(hv - __bfloat162float(hi));
    }
}

// ---------------- LN2 + residuals ----------------
__global__ void ln2_kernel(const float* __restrict__ o2,
                           const float* __restrict__ r1,
                           const float* __restrict__ x,
                           const float* __restrict__ gam,
                           const float* __restrict__ bet,
                           float* __restrict__ out) {
    __shared__ float redS[8], redS2[8];
    int row = blockIdx.x;
    const float* or_ = o2 + (size_t)row * DM;
    const float* rr  = r1 + (size_t)row * DM;
    const float* xr  = x  + (size_t)row * DM;
    float*       wr  = out + (size_t)row * DM;
    int tid = threadIdx.x;

    float a = or_[tid]       + rr[tid];
    float b = or_[tid + 256] + rr[tid + 256];
    float s  = a + b;
    float s2 = a * a + b * b;
#pragma unroll
    for (int off = 16; off; off >>= 1) {
        s  += __shfl_xor_sync(0xffffffffu, s,  off);
        s2 += __shfl_xor_sync(0xffffffffu, s2, off);
    }
    if ((tid & 31) == 0) { redS[tid >> 5] = s; redS2[tid >> 5] = s2; }
    __syncthreads();
    if (tid == 0) {
        float S = 0.f, S2 = 0.f;
#pragma unroll
        for (int w = 0; w < 8; w++) { S += redS[w]; S2 += redS2[w]; }
        redS[0] = S; redS2[0] = S2;
    }
    __syncthreads();
    float mu   = redS[0] * (1.f / 512.f);
    float var  = redS2[0] * (1.f / 512.f) - mu * mu;
    float rstd = rsqrtf(var + 1e-6f);
#pragma unroll
    for (int u = 0; u < 2; u++) {
        int col = tid + u * 256;
        float vv = u ? b : a;
        wr[col] = (vv - mu) * rstd * gam[col] + bet[col] + xr[col];
    }
}

// ================ GEMM core (bf16x3, 128x128 tile) ================
#define GIDESC ((1u << 4) | (1u << 7) | (1u << 10) | ((128u / 8) << 17) | ((128u / 16) << 24))
#define GEMM_DSMEM (2 * 65536 + 1024)

#if HAS_TC
// returns tmem base after all MMAs complete; caller does epilogue + dealloc
__device__ __forceinline__ uint32_t gemm_mainloop_tc(
    const __nv_bfloat16* __restrict__ Ah, const __nv_bfloat16* __restrict__ Al,
    const __nv_bfloat16* __restrict__ Bh, const __nv_bfloat16* __restrict__ Bl,
    int m0, int n0, char* dsm_raw,
    uint64_t* s_mbar, uint32_t* s_tm,
    uint32_t tid, uint32_t wid)
{
    uint32_t raw = smem_u32(dsm_raw);
    uint32_t sb  = (raw + 1023) & ~1023u;
    char* dsm = dsm_raw + (sb - raw);

    uint32_t mb0 = smem_u32(&s_mbar[0]);
    uint32_t mb1 = smem_u32(&s_mbar[1]);

    if (wid == 0) { TC_ALLOC(smem_u32(s_tm), 128); TC_RELINQ(); }
    if (tid == 0) { MBAR_INIT(mb0, 1); MBAR_INIT(mb1, 1); }
    __syncthreads();
    uint32_t tmem = s_tm[0];

    const uint32_t OFF_AH = 0, OFF_AL = 16384, OFF_BH = 32768, OFF_BL = 49152;
    int ph0 = 0, ph1 = 0;
    uint32_t first = 1;

#pragma unroll 1
    for (int c = 0; c < 8; c++) {
        int buf = c & 1;
        uint32_t boff = (uint32_t)buf * 65536u;
        if (c >= 2) {
            if (buf == 0) { mbar_wait(mb0, ph0); ph0 ^= 1; }
            else          { mbar_wait(mb1, ph1); ph1 ^= 1; }
        }
        int k0 = c * 64;

#pragma unroll
        for (int i = 0; i < 4; i++) {
            int idx = i * 256 + (int)tid;
            int r = idx >> 3, g = idx & 7;
            uint32_t o  = (uint32_t)(r * 128 + g * 16);
            uint32_t so = o ^ ((o >> 3) & 0x70);
            size_t ga = (size_t)(m0 + r) * DM + k0 + g * 8;
            size_t gb = (size_t)(n0 + r) * DM + k0 + g * 8;
            *(uint4*)(dsm + boff + OFF_AH + so) = *(const uint4*)(Ah + ga);
            *(uint4*)(dsm + boff + OFF_AL + so) = *(const uint4*)(Al + ga);
            *(uint4*)(dsm + boff + OFF_BH + so) = *(const uint4*)(Bh + gb);
            *(uint4*)(dsm + boff + OFF_BL + so) = *(const uint4*)(Bl + gb);
        }
        __syncthreads();

        if (wid == 0 && elect1()) {
            FENCE_ASYNC_SHARED();
            uint64_t dah = make_desc_sw128(sb + boff + OFF_AH);
            uint64_t dal = make_desc_sw128(sb + boff + OFF_AL);
            uint64_t dbh = make_desc_sw128(sb + boff + OFF_BH);
            uint64_t dbl = make_desc_sw128(sb + boff + OFF_BL);
#pragma unroll
            for (int ks = 0; ks < 4; ks++) {
                mma_f16_ss(tmem, dah + ks * 2, dbh + ks * 2, GIDESC, first ? 0u : 1u);
                first = 0;
                mma_f16_ss(tmem, dah + ks * 2, dbl + ks * 2, GIDESC, 1u);
                mma_f16_ss(tmem, dal + ks * 2, dbh + ks * 2, GIDESC, 1u);
            }
            TC_COMMIT(buf == 0 ? mb0 : mb1);
        }
    }
    mbar_wait(mb1, (uint32_t)ph1);
    TC_FENCE_AFTER();
    return tmem;
}
#else
// SIMT fallback mainloop: computes acc[8][8] for this thread
__device__ __forceinline__ void gemm_mainloop_simt(
    const __nv_bfloat16* __restrict__ Ah, const __nv_bfloat16* __restrict__ Al,
    const __nv_bfloat16* __restrict__ Bh, const __nv_bfloat16* __restrict__ Bl,
    int m0, int n0, char* dsm_raw, uint32_t tid, float acc[8][8])
{
    float* As = (float*)dsm_raw;
    float* Ws = As + 2 * 8 * 132;
    int tx = tid & 15, ty = (int)(tid >> 4);
    int r = tid & 127;
    bool isA = tid < 128;
    const __nv_bfloat16* Ph = isA ? Ah + (size_t)(m0 + r) * DM
                                  : Bh + (size_t)(n0 + r) * DM;
    const __nv_bfloat16* Pl = isA ? Al + (size_t)(m0 + r) * DM
                                  : Bl + (size_t)(n0 + r) * DM;
    int stride = isA ? 132 : 128;
#pragma unroll
    for (int i = 0; i < 8; i++)
#pragma unroll
        for (int j = 0; j < 8; j++) acc[i][j] = 0.f;

    auto stage = [&](int buf, int k0) {
        uint4 vh = *(const uint4*)(Ph + k0);
        uint4 vl = *(const uint4*)(Pl + k0);
        const __nv_bfloat16* bh = (const __nv_bfloat16*)&vh;
        const __nv_bfloat16* bl = (const __nv_bfloat16*)&vl;
        float* dst = (isA ? As + buf * 8 * 132 : Ws + buf * 8 * 128) + r;
#pragma unroll
        for (int k = 0; k < 8; k++)
            dst[k * stride] = __bfloat162float(bh[k]) + __bfloat162float(bl[k]);
    };
    stage(0, 0);
    __syncthreads();
    int buf = 0;
#pragma unroll 1
    for (int k0 = 0; k0 < 512; k0 += 8) {
        if (k0 + 8 < 512) stage(buf ^ 1, k0 + 8);
#pragma unroll
        for (int kk = 0; kk < 8; kk++) {
            float av[8], bv[8];
            const float* ar = As + buf * 8 * 132 + kk * 132;
            const float* wr = Ws + buf * 8 * 128 + kk * 128;
            *(float4*)(av)     = *(const float4*)(ar + ty * 4);
            *(float4*)(av + 4) = *(const float4*)(ar + 64 + ty * 4);
            *(float4*)(bv)     = *(const float4*)(wr + tx * 4);
            *(float4*)(bv + 4) = *(const float4*)(wr + 64 + tx * 4);
#pragma unroll
            for (int i = 0; i < 8; i++)
#pragma unroll
                for (int j = 0; j < 8; j++) acc[i][j] += av[i] * bv[j];
        }
        __syncthreads();
        buf ^= 1;
    }
}
#endif

// ---------------- fused Q/K/V projection (grid.z selects weight + epilogue) ---
__global__ void __launch_bounds__(256, 1)
gemm_qkv_kernel(const __nv_bfloat16* __restrict__ Ah,
                const __nv_bfloat16* __restrict__ Al,
                const __nv_bfloat16* __restrict__ Wh,
                const __nv_bfloat16* __restrict__ Wl,
                __nv_bfloat16* __restrict__ Qh, __nv_bfloat16* __restrict__ Ql,
                __nv_bfloat16* __restrict__ Kh, __nv_bfloat16* __restrict__ Kl,
                __half* __restrict__ Vt, float qscale) {
    extern __shared__ char dsm_raw[];
    uint32_t tid = threadIdx.x, wid = tid >> 5, lid = tid & 31;
    int m0 = blockIdx.x * 128, n0 = blockIdx.y * 128;
    int z = blockIdx.z;
    const __nv_bfloat16* Bh = Wh + (size_t)z * DM * DM;
    const __nv_bfloat16* Bl = Wl + (size_t)z * DM * DM;
    float scale = (z == 0) ? qscale : 1.0f;

#if HAS_TC
    __shared__ __align__(16) uint64_t s_mbar[2];
    __shared__ uint32_t s_tm[1];
    uint32_t tmem = gemm_mainloop_tc(Ah, Al, Bh, Bl, m0, n0, dsm_raw,
                                     s_mbar, s_tm, tid, wid);
    int sub  = wid & 3;
    int colb = (wid >> 2) * 64;
    int row  = m0 + sub * 32 + (int)lid;
    size_t rowoff = (size_t)row * DM + n0 + colb;

    uint32_t d0[32], d1[32];
    tc_ld_x32(d0, tmem + colb);
    tc_ld_x32(d1, tmem + colb + 32);
    TC_WAIT_LD();

    if (z < 2) {
        __nv_bfloat16* Ch = (z == 0) ? Qh : Kh;
        __nv_bfloat16* Cl = (z == 0) ? Ql : Kl;
        uint32_t hw[32], lw[32];
#pragma unroll
        for (int m = 0; m < 16; m++) {
            float v0 = __uint_as_float(d0[2*m])   * scale;
            float v1 = __uint_as_float(d0[2*m+1]) * scale;
            __nv_bfloat162 h2 = __floats2bfloat162_rn(v0, v1);
            __nv_bfloat162 l2 = __floats2bfloat162_rn(v0 - __bfloat162float(h2.x),
                                                      v1 - __bfloat162float(h2.y));
            hw[m] = *(uint32_t*)&h2; lw[m] = *(uint32_t*)&l2;
        }
#pragma unroll
        for (int m = 0; m < 16; m++) {
            float v0 = __uint_as_float(d1[2*m])   * scale;
            float v1 = __uint_as_float(d1[2*m+1]) * scale;
            __nv_bfloat162 h2 = __floats2bfloat162_rn(v0, v1);
            __nv_bfloat162 l2 = __floats2bfloat162_rn(v0 - __bfloat162float(h2.x),
                                                      v1 - __bfloat162float(h2.y));
            hw[16 + m] = *(uint32_t*)&h2; lw[16 + m] = *(uint32_t*)&l2;
        }
#pragma unroll
        for (int u = 0; u < 8; u++) {
            *(uint4*)(Ch + rowoff + u * 8) =
                make_uint4(hw[4*u], hw[4*u+1], hw[4*u+2], hw[4*u+3]);
            *(uint4*)(Cl + rowoff + u * 8) =
                make_uint4(lw[4*u], lw[4*u+1], lw[4*u+2], lw[4*u+3]);
        }
    } else {
        // V: fp16 transposed store [bh][dim][key]
        int b = row >> 11, t = row & (SEQ - 1);
#pragma unroll
        for (int j = 0; j < 32; j++) {
            int c = n0 + colb + j;
            size_t o = ((size_t)((b << 3) + (c >> 6)) * 64 + (c & 63)) * SEQ + t;
            Vt[o] = __float2half(__uint_as_float(d0[j]));
        }
#pragma unroll
        for (int j = 0; j < 32; j++) {
            int c = n0 + colb + 32 + j;
            size_t o = ((size_t)((b << 3) + (c >> 6)) * 64 + (c & 63)) * SEQ + t;
            Vt[o] = __float2half(__uint_as_float(d1[j]));
        }
    }
    TC_FENCE_BEFORE();
    __syncthreads();
    if (wid == 0) TC_DEALLOC(tmem, 128);
#else
    float acc[8][8];
    gemm_mainloop_simt(Ah, Al, Bh, Bl, m0, n0, dsm_raw, tid, acc);
    int tx = tid & 15, ty = (int)(tid >> 4);
#pragma unroll
    for (int i = 0; i < 8; i++) {
        int row = m0 + ((i < 4) ? (ty * 4 + i) : (64 + ty * 4 + i - 4));
#pragma unroll
        for (int j = 0; j < 8; j++) {
            int col = n0 + ((j < 4) ? (tx * 4 + j) : (64 + tx * 4 + j - 4));
            float v = acc[i][j] * scale;
            if (z < 2) {
                __nv_bfloat16* Ch = (z == 0) ? Qh : Kh;
                __nv_bfloat16* Cl = (z == 0) ? Ql : Kl;
                __nv_bfloat16 h = __float2bfloat16(v);
                Ch[(size_t)row * DM + col] = h;
                Cl[(size_t)row * DM + col] = __float2bfloat16(v - __bfloat162float(h));
            } else {
                int b = row >> 11, t = row & (SEQ - 1);
                size_t o = ((size_t)((b << 3) + (col >> 6)) * 64 + (col & 63)) * SEQ + t;
                Vt[o] = __float2half(v);
            }
        }
    }
#endif
}

// ---------------- FC projection (fp32 out) ----------------
__global__ void __launch_bounds__(256, 1)
gemm_fc_kernel(const __nv_bfloat16* __restrict__ Ah,
               const __nv_bfloat16* __restrict__ Al,
               const __nv_bfloat16* __restrict__ Bh,
               const __nv_bfloat16* __restrict__ Bl,
               float* __restrict__ C) {
    extern __shared__ char dsm_raw[];
    uint32_t tid = threadIdx.x, wid = tid >> 5, lid = tid & 31;
    int m0 = blockIdx.x * 128, n0 = blockIdx.y * 128;
#if HAS_TC
    __shared__ __align__(16) uint64_t s_mbar[2];
    __shared__ uint32_t s_tm[1];
    uint32_t tmem = gemm_mainloop_tc(Ah, Al, Bh, Bl, m0, n0, dsm_raw,
                                     s_mbar, s_tm, tid, wid);
    int sub  = wid & 3;
    int colb = (wid >> 2) * 64;
    int row  = m0 + sub * 32 + (int)lid;
    float* Cr = C + (size_t)row * DM + n0 + colb;

    uint32_t d0[32], d1[32];
    tc_ld_x32(d0, tmem + colb);
    tc_ld_x32(d1, tmem + colb + 32);
    TC_WAIT_LD();
#pragma unroll
    for (int j = 0; j < 8; j++)
        *(float4*)(Cr + j * 4) = make_float4(
            __uint_as_float(d0[4*j]),   __uint_as_float(d0[4*j+1]),
            __uint_as_float(d0[4*j+2]), __uint_as_float(d0[4*j+3]));
#pragma unroll
    for (int j = 0; j < 8; j++)
        *(float4*)(Cr + 32 + j * 4) = make_float4(
            __uint_as_float(d1[4*j]),   __uint_as_float(d1[4*j+1]),
            __uint_as_float(d1[4*j+2]), __uint_as_float(d1[4*j+3]));
    TC_FENCE_BEFORE();
    __syncthreads();
    if (wid == 0) TC_DEALLOC(tmem, 128);
#else
    float acc[8][8];
    gemm_mainloop_simt(Ah, Al, Bh, Bl, m0, n0, dsm_raw, tid, acc);
    int tx = tid & 15, ty = (int)(tid >> 4);
#pragma unroll
    for (int i = 0; i < 8; i++) {
        int row = m0 + ((i < 4) ? (ty * 4 + i) : (64 + ty * 4 + i - 4));
#pragma unroll
        for (int j = 0; j < 8; j++) {
            int col = n0 + ((j < 4) ? (tx * 4 + j) : (64 + tx * 4 + j - 4));
            C[(size_t)row * DM + col] = acc[i][j];
        }
    }
#endif
}

// ================ attention ================
#define AIDESC_S  ((1u << 4) | (1u << 7) | (1u << 10) | ((64u / 8) << 17) | ((128u / 16) << 24))
#define AIDESC_PV ((1u << 4) | ((64u / 8) << 17) | ((128u / 16) << 24))
#define ATTN_DSMEM 100352

#if HAS_TC
__global__ void __launch_bounds__(256)
attn_kernel(const __nv_bfloat16* __restrict__ Qh, const __nv_bfloat16* __restrict__ Ql,
            const __nv_bfloat16* __restrict__ Kh, const __nv_bfloat16* __restrict__ Kl,
            const __half* __restrict__ Vt,
            __nv_bfloat16* __restrict__ Oh, __nv_bfloat16* __restrict__ Ol) {
    extern __shared__ char dsm_raw[];
    __shared__ __align__(16) uint64_t s_mbar[2];
    __shared__ uint32_t s_tm[1];
    uint32_t tid = threadIdx.x, wid = tid >> 5, lane = tid & 31;
    int qt = (int)(gridDim.x - 1) - (int)blockIdx.x;     // heavy tiles first
    int bh = blockIdx.y, bb = bh >> 3, hd = bh & 7;

    uint32_t raw = smem_u32(dsm_raw);
    uint32_t sb  = (raw + 1023) & ~1023u;
    char* dsm = dsm_raw + (sb - raw);

    const uint32_t OFF_QH = 0,     OFF_QL = 16384,
                   OFF_KH = 32768, OFF_KL = 49152,   // +buf*8192 each (db)
                   OFF_V  = 65536,                   // +buf*8192 (db, fp16)
                   OFF_P  = 81920,                   // fp16 single
                   OFF_L  = 98304;

    uint32_t mbS  = smem_u32(&s_mbar[0]);
    uint32_t mbPV = smem_u32(&s_mbar[1]);
    if (wid == 0) { TC_ALLOC(smem_u32(s_tm), 128); TC_RELINQ(); }
    if (tid == 0) { MBAR_INIT(mbS, 1); MBAR_INIT(mbPV, 1); }
    __syncthreads();
    uint32_t tmem = s_tm[0];

    size_t rowbase = (size_t)bb * SEQ;

    // load Q tile (pre-scaled bf16 splits)
    {
        const __nv_bfloat16* qhp = Qh + (rowbase + (size_t)qt * 128) * DM + hd * 64;
        const __nv_bfloat16* qlp = Ql + (rowbase + (size_t)qt * 128) * DM + hd * 64;
#pragma unroll
        for (int i = 0; i < 4; i++) {
            int idx = i * 256 + (int)tid;
            int r = idx >> 3, g = idx & 7;
            uint32_t o = (uint32_t)(r * 128 + g * 16), so = o ^ ((o >> 3) & 0x70);
            *(uint4*)(dsm + OFF_QH + so) = *(const uint4*)(qhp + (size_t)r * DM + g * 8);
            *(uint4*)(dsm + OFF_QL + so) = *(const uint4*)(qlp + (size_t)r * DM + g * 8);
        }
    }

    int sub = wid & 3, half = (int)(wid >> 2);
    int rl = sub * 32 + (int)lane;
    int grow = qt * 128 + rl;
    float lsum = 0.f;
    uint32_t phS = 0, phPV = 0;
    int ktmax = 2 * qt + 1;

#pragma unroll 1
    for (int kt = 0; kt <= ktmax; kt++) {
        int buf = kt & 1;
        uint32_t kb  = OFF_KH + (uint32_t)buf * 8192u;
        uint32_t klb = OFF_KL + (uint32_t)buf * 8192u;
        uint32_t vb  = OFF_V  + (uint32_t)buf * 8192u;

        const __nv_bfloat16* khp = Kh + (rowbase + (size_t)kt * 64) * DM + hd * 64;
        const __nv_bfloat16* klp = Kl + (rowbase + (size_t)kt * 64) * DM + hd * 64;
        const __half*        vhp = Vt + ((size_t)bh * 64) * SEQ + (size_t)kt * 64;
#pragma unroll
        for (int i = 0; i < 2; i++) {
            int idx = i * 256 + (int)tid;
            int r = idx >> 3, g = idx & 7;
            uint32_t o = (uint32_t)(r * 128 + g * 16), so = o ^ ((o >> 3) & 0x70);
            *(uint4*)(dsm + kb  + so) = *(const uint4*)(khp + (size_t)r * DM + g * 8);
            *(uint4*)(dsm + klb + so) = *(const uint4*)(klp + (size_t)r * DM + g * 8);
            *(uint4*)(dsm + vb  + so) = *(const uint4*)(vhp + (size_t)r * SEQ + g * 8);
        }
        __syncthreads();

        if (wid == 0 && elect1()) {
            FENCE_ASYNC_SHARED();
            uint64_t dqh = make_desc_sw128(sb + OFF_QH);
            uint64_t dql = make_desc_sw128(sb + OFF_QL);
            uint64_t dkh = make_desc_sw128(sb + kb);
            uint64_t dkl = make_desc_sw128(sb + klb);
#pragma unroll
            for (int ks = 0; ks < 4; ks++)
                mma_f16_ss(tmem, dqh + ks * 2, dkh + ks * 2, AIDESC_S, ks ? 1u : 0u);
#pragma unroll
            for (int ks = 0; ks < 4; ks++)
                mma_f16_ss(tmem, dqh + ks * 2, dkl + ks * 2, AIDESC_S, 1u);
#pragma unroll
            for (int ks = 0; ks < 4; ks++)
                mma_f16_ss(tmem, dql + ks * 2, dkh + ks * 2, AIDESC_S, 1u);
            TC_COMMIT(mbS);
        }
        mbar_wait(mbS, phS); phS ^= 1;
        TC_FENCE_AFTER();

        uint32_t sreg[32];
        tc_ld_x32(sreg, tmem + half * 32);
        TC_WAIT_LD();

        int jmax = grow - (kt * 64 + half * 32);
        if (kt) { mbar_wait(mbPV, phPV); phPV ^= 1; }

        uint32_t pbase = (uint32_t)(rl * 128 + half * 64);
#pragma unroll
        for (int gj = 0; gj < 4; gj++) {
            uint32_t w[4];
#pragma unroll
            for (int m = 0; m < 4; m++) {
                int j0 = gj * 8 + m * 2;
                float p0 = (j0     <= jmax) ? fast_exp2(__uint_as_float(sreg[j0]))     : 0.f;
                float p1 = (j0 + 1 <= jmax) ? fast_exp2(__uint_as_float(sreg[j0 + 1])) : 0.f;
                lsum += p0 + p1;
                __half2 h2 = __floats2half2_rn(p0, p1);
                w[m] = *(uint32_t*)&h2;
            }
            uint32_t o = pbase + gj * 16, so = o ^ ((o >> 3) & 0x70);
            *(uint4*)(dsm + OFF_P + so) = make_uint4(w[0], w[1], w[2], w[3]);
        }
        __syncthreads();

        if (wid == 0 && elect1()) {
            FENCE_ASYNC_SHARED();
            uint64_t dp = make_desc_sw128(sb + OFF_P);
            uint64_t dv = make_desc_sw128(sb + vb);
#pragma unroll
            for (int ks = 0; ks < 4; ks++)
                mma_f16_ss(tmem + 64, dp + ks * 2, dv + ks * 2, AIDESC_PV,
                           (kt == 0 && ks == 0) ? 0u : 1u);
            TC_COMMIT(mbPV);
        }
    }

    mbar_wait(mbPV, phPV);
    TC_FENCE_AFTER();

    float* sl = (float*)(dsm + OFF_L);
    sl[rl * 2 + half] = lsum;
    __syncthreads();
    float inv = 1.f / (sl[rl * 2] + sl[rl * 2 + 1]);

    uint32_t oreg[32];
    tc_ld_x32(oreg, tmem + 64 + half * 32);
    TC_WAIT_LD();
    TC_FENCE_BEFORE();

    size_t obase = (rowbase + (size_t)grow) * DM + hd * 64 + half * 32;
    uint32_t hw[16], lw[16];
#pragma unroll
    for (int m = 0; m < 16; m++) {
        float v0 = __uint_as_float(oreg[2*m])   * inv;
        float v1 = __uint_as_float(oreg[2*m+1]) * inv;
        __nv_bfloat162 h2 = __floats2bfloat162_rn(v0, v1);
        __nv_bfloat162 l2 = __floats2bfloat162_rn(v0 - __bfloat162float(h2.x),
                                                  v1 - __bfloat162float(h2.y));
        hw[m] = *(uint32_t*)&h2; lw[m] = *(uint32_t*)&l2;
    }
#pragma unroll
    for (int u = 0; u < 4; u++) {
        *(uint4*)(Oh + obase + u * 8) = make_uint4(hw[4*u], hw[4*u+1], hw[4*u+2], hw[4*u+3]);
        *(uint4*)(Ol + obase + u * 8) = make_uint4(lw[4*u], lw[4*u+1], lw[4*u+2], lw[4*u+3]);
    }
    __syncthreads();
    if (wid == 0) TC_DEALLOC(tmem, 128);
}

#else  // ---------------- SIMT fallback attention ----------------
__global__ void __launch_bounds__(256)
attn_kernel(const __nv_bfloat16* __restrict__ Qh, const __nv_bfloat16* __restrict__ Ql,
            const __nv_bfloat16* __restrict__ Kh, const __nv_bfloat16* __restrict__ Kl,
            const __half* __restrict__ Vt,
            __nv_bfloat16* __restrict__ Oh, __nv_bfloat16* __restrict__ Ol) {
    extern __shared__ float sm[];
    float* sQ = sm;                 // 128 x 68
    float* sK = sQ + 128 * 68;      // 64 x 68
    float* sV = sK + 64 * 68;       // 64 x 64
    float* sP = sV + 64 * 64;       // 128 x 68

    int qt = (int)(gridDim.x - 1) - (int)blockIdx.x;
    int bh = blockIdx.y;
    int bb = bh >> 3, hd = bh & 7;
    int tid = threadIdx.x;
    int tx = tid & 15, ty = tid >> 4;
    size_t base = ((size_t)bb * SEQ) * DM + (size_t)hd * DK;

    for (int idx = tid; idx < 128 * 64; idx += 256) {
        int r = idx >> 6, c = idx & 63;
        size_t o = base + (size_t)(qt * 128 + r) * DM + c;
        sQ[r * 68 + c] = __bfloat162float(Qh[o]) + __bfloat162float(Ql[o]);
    }

    float Oacc[8][4], m_i[8], l_i[8];
#pragma unroll
    for (int i = 0; i < 8; i++) {
        m_i[i] = -1e30f; l_i[i] = 0.f;
#pragma unroll
        for (int j = 0; j < 4; j++) Oacc[i][j] = 0.f;
    }

    int ktmax = 2 * qt + 1;
    for (int kt = 0; kt <= ktmax; kt++) {
        for (int idx = tid; idx < 64 * 64; idx += 256) {
            int r = idx >> 6, c = idx & 63;
            size_t ga = base + (size_t)(kt * 64 + r) * DM + c;
            sK[r * 68 + c] = __bfloat162float(Kh[ga]) + __bfloat162float(Kl[ga]);
            sV[r * 64 + c] = __half2float(Vt[((size_t)bh * 64 + c) * SEQ + kt * 64 + r]);
        }
        __syncthreads();

        float s[8][4];
#pragma unroll
        for (int i = 0; i < 8; i++)
#pragma unroll
            for (int j = 0; j < 4; j++) s[i][j] = 0.f;
#pragma unroll
        for (int d4 = 0; d4 < 16; d4++) {
            float4 kv[4];
#pragma unroll
            for (int j = 0; j < 4; j++)
                kv[j] = *(const float4*)&sK[(tx + 16 * j) * 68 + d4 * 4];
#pragma unroll
            for (int i = 0; i < 8; i++) {
                float4 qv = *(const float4*)&sQ[(ty + 16 * i) * 68 + d4 * 4];
#pragma unroll
                for (int j = 0; j < 4; j++)
                    s[i][j] += qv.x * kv[j].x + qv.y * kv[j].y +
                               qv.z * kv[j].z + qv.w * kv[j].w;
            }
        }
        if (kt >= 2 * qt) {
#pragma unroll
            for (int i = 0; i < 8; i++) {
                int grow = qt * 128 + ty + 16 * i;
#pragma unroll
                for (int j = 0; j < 4; j++)
                    if (kt * 64 + tx + 16 * j > grow) s[i][j] = -1e30f;
            }
        }
#pragma unroll
        for (int i = 0; i < 8; i++) {
            float mt = fmaxf(fmaxf(s[i][0], s[i][1]), fmaxf(s[i][2], s[i][3]));
#pragma unroll
            for (int off = 8; off; off >>= 1)
                mt = fmaxf(mt, __shfl_xor_sync(0xffffffffu, mt, off));
            float mn = fmaxf(m_i[i], mt);
            float corr = exp2f(m_i[i] - mn);
            m_i[i] = mn;
            float rs = 0.f;
#pragma unroll
            for (int j = 0; j < 4; j++) {
                float p = exp2f(s[i][j] - mn);
                s[i][j] = p; rs += p;
            }
#pragma unroll
            for (int off = 8; off; off >>= 1)
                rs += __shfl_xor_sync(0xffffffffu, rs, off);
            l_i[i] = l_i[i] * corr + rs;
#pragma unroll
            for (int j = 0; j < 4; j++) Oacc[i][j] *= corr;
#pragma unroll
            for (int j = 0; j < 4; j++)
                sP[(ty + 16 * i) * 68 + tx + 16 * j] = s[i][j];
        }
        __syncthreads();
#pragma unroll 4
        for (int k = 0; k < 64; k += 4) {
            float4 vv0 = *(const float4*)&sV[(k + 0) * 64 + tx * 4];
            float4 vv1 = *(const float4*)&sV[(k + 1) * 64 + tx * 4];
            float4 vv2 = *(const float4*)&sV[(k + 2) * 64 + tx * 4];
            float4 vv3 = *(const float4*)&sV[(k + 3) * 64 + tx * 4];
#pragma unroll
            for (int i = 0; i < 8; i++) {
                float4 pv = *(const float4*)&sP[(ty + 16 * i) * 68 + k];
                Oacc[i][0] += pv.x * vv0.x + pv.y * vv1.x + pv.z * vv2.x + pv.w * vv3.x;
                Oacc[i][1] += pv.x * vv0.y + pv.y * vv1.y + pv.z * vv2.y + pv.w * vv3.y;
                Oacc[i][2] += pv.x * vv0.z + pv.y * vv1.z + pv.z * vv2.z + pv.w * vv3.z;
                Oacc[i][3] += pv.x * vv0.w + pv.y * vv1.w + pv.z * vv2.w + pv.w * vv3.w;
            }
        }
        __syncthreads();
    }
#pragma unroll
    for (int i = 0; i < 8; i++) {
        float inv = 1.f / l_i[i];
        size_t rowa = base + (size_t)(qt * 128 + ty + 16 * i) * DM + tx * 4;
#pragma unroll
        for (int j = 0; j < 4; j++) {
            float v = Oacc[i][j] * inv;
            __nv_bfloat16 h = __float2bfloat16(v);
            Oh[rowa + j] = h;
            Ol[rowa + j] = __float2bfloat16(v - __bfloat162float(h));
        }
    }
}
#endif

// ---------------- launch ----------------
extern "C" void kernel_launch(void* const* d_in, const int* in_sizes, int n_in,
                              void* d_out, int out_size) {
    const float* x     = (const float*)d_in[0];
    const float* ln1_g = (const float*)d_in[1];
    const float* ln1_b = (const float*)d_in[2];
    const float* wq    = (const float*)d_in[3];
    const float* wk    = (const float*)d_in[4];
    const float* wv    = (const float*)d_in[5];
    const float* wfc   = (const float*)d_in[6];
    const float* ln2_g = (const float*)d_in[7];
    const float* ln2_b = (const float*)d_in[8];
    float* out = (float*)d_out;

    float *ppe, *ph, *pfc;
    __nv_bfloat16 *pwh, *pwl, *pah, *pal, *pqh, *pql, *pkh, *pkl, *poh, *pol;
    __half *pvt;
    cudaGetSymbolAddress((void**)&ppe,  g_pe);
    cudaGetSymbolAddress((void**)&ph,   g_h);
    cudaGetSymbolAddress((void**)&pfc,  g_fc);
    cudaGetSymbolAddress((void**)&pwh,  g_wth);
    cudaGetSymbolAddress((void**)&pwl,  g_wtl);
    cudaGetSymbolAddress((void**)&pah,  g_ah);
    cudaGetSymbolAddress((void**)&pal,  g_al);
    cudaGetSymbolAddress((void**)&pqh,  g_qh);
    cudaGetSymbolAddress((void**)&pql,  g_ql);
    cudaGetSymbolAddress((void**)&pkh,  g_kh);
    cudaGetSymbolAddress((void**)&pkl,  g_kl);
    cudaGetSymbolAddress((void**)&poh,  g_oh);
    cudaGetSymbolAddress((void**)&pol,  g_ol);
    cudaGetSymbolAddress((void**)&pvt,  g_vt);

    cudaFuncSetAttribute(attn_kernel,
                         cudaFuncAttributeMaxDynamicSharedMemorySize, ATTN_DSMEM);
    cudaFuncSetAttribute(gemm_qkv_kernel,
                         cudaFuncAttributeMaxDynamicSharedMemorySize, GEMM_DSMEM);
    cudaFuncSetAttribute(gemm_fc_kernel,
                         cudaFuncAttributeMaxDynamicSharedMemorySize, GEMM_DSMEM);

    const float qscale = 0.125f * 1.4426950408889634f;

    // 1: pe
    pe_kernel<<<SEQ, 256>>>(ppe);
    // 2: wsplit q,k,v
    dim3 wt(32, 8);
    wsplit3_kernel<<<dim3(16, 16, 3), wt>>>(wq, wk, wv, pwh, pwl);
    // 3: wsplit fc
    wsplit_kernel<<<dim3(16, 16), wt>>>(wfc, pwh + 3 * (size_t)DM * DM,
                                             pwl + 3 * (size_t)DM * DM);
    // 4: ln1 + pe + split
    ln1_pos_kernel<<<ROWS, 256>>>(x, ln1_g, ln1_b, ppe, ph, pah, pal);
    // 5: fused q/k/v projections
    gemm_qkv_kernel<<<dim3(ROWS / 128, DM / 128, 3), 256, GEMM_DSMEM>>>(
        pah, pal, pwh, pwl, pqh, pql, pkh, pkl, pvt, qscale);
    // 6: attention  (ncu capture target)
    dim3 ga(SEQ / 128, BATCH * NH);
    attn_kernel<<<ga, 256, ATTN_DSMEM>>>(pqh, pql, pkh, pkl, pvt, poh, pol);
    // 7: fc
    gemm_fc_kernel<<<dim3(ROWS / 128, DM / 128), 256, GEMM_DSMEM>>>(
        poh, pol, pwh + 3 * (size_t)DM * DM, pwl + 3 * (size_t)DM * DM, pfc);
    // 8: ln2
    ln2_kernel<<<ROWS, 256>>>(pfc, ph, x, ln2_g, ln2_b, out);
}